// round 1
// baseline (speedup 1.0000x reference)
#include <cuda_runtime.h>
#include <math.h>

// ---------------- problem constants ----------------
constexpr int cB = 16, cS = 512, cE = 768, cH = 2, cHD = 384;
constexpr int cFF = 256, cL = 3, cENC = 128, cIN = 234;
constexpr int cM = cB * cS;            // 8192 rows
constexpr float NEGBIG = -1e9f;

// ---------------- device scratch (static: no allocs allowed) ----------------
__device__ float g_x   [cM * cE];            // current activation
__device__ float g_a   [cM * cE];            // attention concat output
__device__ float g_h   [cM * cE];            // residual branch
__device__ float g_mem [cM * cE];            // encoder memory
__device__ float g_enc [cM * cENC];
__device__ float g_qkv [cM * 3 * cE];        // SA qkv / CA q / FFN hidden scratch
__device__ float g_sc  [cB * cH * cS * cS];  // attention scores
__device__ float g_cakv[cL * cM * 2 * cE];   // cached cross-attn K,V per layer

// ---------------- GEMM: C = A * op(B) + bias, batched with 2-level strides ----
// TRANSB: B is [N,K] (torch weight), else B is [K,N].
// Epilogue: *scale, +NEG if causal && col>row, +bias, relu.
#define BM 64
#define BN 64
#define BKT 16

template<bool TRANSB, bool RELU, bool CAUSAL>
__global__ void __launch_bounds__(256)
gemm_k(int M, int N, int K,
       const float* __restrict__ A, int lda, long long sAo, long long sAi,
       const float* __restrict__ B, int ldb, long long sBo, long long sBi,
       float* __restrict__ C, int ldc, long long sCo, long long sCi,
       const float* __restrict__ bias, float scale, int innerH)
{
    int z  = blockIdx.z;
    int zo = z / innerH, zi = z - zo * innerH;
    A += zo * sAo + zi * sAi;
    B += zo * sBo + zi * sBi;
    C += zo * sCo + zi * sCi;

    __shared__ float As[BKT][BM];
    __shared__ float Bs[BKT][BN];

    int tx = threadIdx.x, ty = threadIdx.y;
    int tid  = ty * 16 + tx;
    int row0 = blockIdx.y * BM;
    int col0 = blockIdx.x * BN;

    float acc[4][4] = {};

    for (int k0 = 0; k0 < K; k0 += BKT) {
        #pragma unroll
        for (int t = 0; t < 4; t++) {
            int idx = tid + t * 256;
            int m = idx >> 4, kk = idx & 15;
            int gr = row0 + m, gk = k0 + kk;
            As[kk][m] = (gr < M && gk < K) ? A[(size_t)gr * lda + gk] : 0.f;
        }
        if (TRANSB) {
            #pragma unroll
            for (int t = 0; t < 4; t++) {
                int idx = tid + t * 256;
                int n = idx >> 4, kk = idx & 15;
                int gn = col0 + n, gk = k0 + kk;
                Bs[kk][n] = (gn < N && gk < K) ? B[(size_t)gn * ldb + gk] : 0.f;
            }
        } else {
            #pragma unroll
            for (int t = 0; t < 4; t++) {
                int idx = tid + t * 256;
                int kk = idx >> 6, n = idx & 63;
                int gn = col0 + n, gk = k0 + kk;
                Bs[kk][n] = (gn < N && gk < K) ? B[(size_t)gk * ldb + gn] : 0.f;
            }
        }
        __syncthreads();
        #pragma unroll
        for (int kk = 0; kk < BKT; kk++) {
            float av[4], bv[4];
            #pragma unroll
            for (int i = 0; i < 4; i++) av[i] = As[kk][ty + 16 * i];
            #pragma unroll
            for (int j = 0; j < 4; j++) bv[j] = Bs[kk][tx + 16 * j];
            #pragma unroll
            for (int i = 0; i < 4; i++)
                #pragma unroll
                for (int j = 0; j < 4; j++)
                    acc[i][j] += av[i] * bv[j];
        }
        __syncthreads();
    }

    #pragma unroll
    for (int i = 0; i < 4; i++) {
        int r = row0 + ty + 16 * i;
        if (r >= M) continue;
        #pragma unroll
        for (int j = 0; j < 4; j++) {
            int c = col0 + tx + 16 * j;
            if (c >= N) continue;
            float v = acc[i][j] * scale;
            if (CAUSAL && c > r) v += NEGBIG;
            if (bias) v += bias[c];
            if (RELU) v = fmaxf(v, 0.f);
            C[(size_t)r * ldc + c] = v;
        }
    }
}

// ---------------- block reduce helper ----------------
__device__ __forceinline__ float blockReduceSum(float v, float* s) {
    int tid = threadIdx.x;
    int nw  = blockDim.x >> 5;
    #pragma unroll
    for (int o = 16; o; o >>= 1) v += __shfl_xor_sync(0xffffffffu, v, o);
    if ((tid & 31) == 0) s[tid >> 5] = v;
    __syncthreads();
    if (tid < 32) {
        float t = (tid < nw) ? s[tid] : 0.f;
        #pragma unroll
        for (int o = 16; o; o >>= 1) t += __shfl_xor_sync(0xffffffffu, t, o);
        if (tid == 0) s[0] = t;
    }
    __syncthreads();
    float r = s[0];
    __syncthreads();
    return r;
}

// ---------------- row softmax ----------------
__global__ void softmax_k(float* __restrict__ x, int ncols) {
    x += (size_t)blockIdx.x * ncols;
    int tid = threadIdx.x;
    __shared__ float red[32];

    float mx = -3.4e38f;
    for (int i = tid; i < ncols; i += blockDim.x) mx = fmaxf(mx, x[i]);
    #pragma unroll
    for (int o = 16; o; o >>= 1) mx = fmaxf(mx, __shfl_xor_sync(0xffffffffu, mx, o));
    if ((tid & 31) == 0) red[tid >> 5] = mx;
    __syncthreads();
    if (tid < 32) {
        float t = (tid < (blockDim.x >> 5)) ? red[tid] : -3.4e38f;
        #pragma unroll
        for (int o = 16; o; o >>= 1) t = fmaxf(t, __shfl_xor_sync(0xffffffffu, t, o));
        if (tid == 0) red[0] = t;
    }
    __syncthreads();
    mx = red[0];
    __syncthreads();

    float sum = 0.f;
    for (int i = tid; i < ncols; i += blockDim.x) {
        float e = expf(x[i] - mx);
        x[i] = e;
        sum += e;
    }
    sum = blockReduceSum(sum, red);
    float inv = 1.f / sum;
    for (int i = tid; i < ncols; i += blockDim.x) x[i] *= inv;
}

// ---------------- fused x = LayerNorm(x + h) * g + b (in place) ----------------
__global__ void add_ln_k(float* __restrict__ x, const float* __restrict__ h,
                         const float* __restrict__ g, const float* __restrict__ b,
                         int ncols)
{
    size_t base = (size_t)blockIdx.x * ncols;
    int tid = threadIdx.x;
    __shared__ float red[32];

    float v[4];
    float sum = 0.f;
    int c = 0;
    for (int i = tid; i < ncols; i += blockDim.x, c++) {
        v[c] = x[base + i] + h[base + i];
        sum += v[c];
    }
    sum = blockReduceSum(sum, red);
    float mu = sum / ncols;

    float sq = 0.f;
    c = 0;
    for (int i = tid; i < ncols; i += blockDim.x, c++) {
        float d = v[c] - mu;
        sq += d * d;
    }
    sq = blockReduceSum(sq, red);
    float rstd = rsqrtf(sq / ncols + 1e-5f);

    c = 0;
    for (int i = tid; i < ncols; i += blockDim.x, c++)
        x[base + i] = (v[c] - mu) * rstd * g[i] + b[i];
}

// ---------------- scheduled sampling mix ----------------
__global__ void mix_k(float* __restrict__ x, const float* __restrict__ labels,
                      const float* __restrict__ sr, const int* __restrict__ steps,
                      int total)
{
    int i = blockIdx.x * blockDim.x + threadIdx.x;
    if (i >= total) return;
    int s = (i / cE) % cS;
    int b = i / (cE * cS);
    float thr = (float)(*steps) / 200000.0f;
    if (sr[s * cB + b] >= thr) x[i] = labels[i];
}

// ---------------- host-side gemm dispatch ----------------
static void launch_gemm(bool transB, bool relu, bool causal,
                        int M, int N, int K,
                        const float* A, int lda, long long sAo, long long sAi,
                        const float* B, int ldb, long long sBo, long long sBi,
                        float* C, int ldc, long long sCo, long long sCi,
                        const float* bias, float scale, int nz, int innerH)
{
    dim3 blk(16, 16);
    dim3 grd((N + BN - 1) / BN, (M + BM - 1) / BM, nz);
    if (!transB)
        gemm_k<false, false, false><<<grd, blk>>>(M, N, K, A, lda, sAo, sAi,
            B, ldb, sBo, sBi, C, ldc, sCo, sCi, bias, scale, innerH);
    else if (causal)
        gemm_k<true, false, true><<<grd, blk>>>(M, N, K, A, lda, sAo, sAi,
            B, ldb, sBo, sBi, C, ldc, sCo, sCi, bias, scale, innerH);
    else if (relu)
        gemm_k<true, true, false><<<grd, blk>>>(M, N, K, A, lda, sAo, sAi,
            B, ldb, sBo, sBi, C, ldc, sCo, sCi, bias, scale, innerH);
    else
        gemm_k<true, false, false><<<grd, blk>>>(M, N, K, A, lda, sAo, sAi,
            B, ldb, sBo, sBi, C, ldc, sCo, sCi, bias, scale, innerH);
}

extern "C" void kernel_launch(void* const* d_in, const int* in_sizes, int n_in,
                              void* d_out, int out_size)
{
    const float* batch    = (const float*)d_in[0];
    const float* labels   = (const float*)d_in[1];
    const float* sched    = (const float*)d_in[2];
    const int*   steps    = (const int*)  d_in[3];
    const float* W_pre    = (const float*)d_in[4];
    const float* b_pre    = (const float*)d_in[5];
    const float* W_enc    = (const float*)d_in[6];
    const float* b_enc    = (const float*)d_in[7];
    const float* W_e2d    = (const float*)d_in[8];
    const float* b_e2d    = (const float*)d_in[9];
    const float* sa_in_w  = (const float*)d_in[10];
    const float* sa_in_b  = (const float*)d_in[11];
    const float* sa_out_w = (const float*)d_in[12];
    const float* sa_out_b = (const float*)d_in[13];
    const float* ca_in_w  = (const float*)d_in[14];
    const float* ca_in_b  = (const float*)d_in[15];
    const float* ca_out_w = (const float*)d_in[16];
    const float* ca_out_b = (const float*)d_in[17];
    const float* w1       = (const float*)d_in[18];
    const float* b1       = (const float*)d_in[19];
    const float* w2       = (const float*)d_in[20];
    const float* b2       = (const float*)d_in[21];
    const float* g1       = (const float*)d_in[22];
    const float* be1      = (const float*)d_in[23];
    const float* g2       = (const float*)d_in[24];
    const float* be2      = (const float*)d_in[25];
    const float* g3       = (const float*)d_in[26];
    const float* be3      = (const float*)d_in[27];

    float *x, *a, *h, *mem, *enc, *qkv, *sc, *cakv;
    cudaGetSymbolAddress((void**)&x,    g_x);
    cudaGetSymbolAddress((void**)&a,    g_a);
    cudaGetSymbolAddress((void**)&h,    g_h);
    cudaGetSymbolAddress((void**)&mem,  g_mem);
    cudaGetSymbolAddress((void**)&enc,  g_enc);
    cudaGetSymbolAddress((void**)&qkv,  g_qkv);
    cudaGetSymbolAddress((void**)&sc,   g_sc);
    cudaGetSymbolAddress((void**)&cakv, g_cakv);

    const float atscale = 1.0f / sqrtf((float)cHD);
    const long long sQb = (long long)cS * 3 * cE;   // qkv batch(b) stride
    const long long sKVb = (long long)cS * 2 * cE;  // cakv batch(b) stride
    const long long sScb = (long long)cH * cS * cS; // scores b stride
    const long long sSch = (long long)cS * cS;      // scores h stride
    const long long sAb = (long long)cS * cE;       // attn-out b stride

    // ---- prenet + encoder projection chain ----
    launch_gemm(false, false, false, cM, cE, cIN,
                batch, cIN, 0, 0, W_pre, cE, 0, 0, a, cE, 0, 0, b_pre, 1.f, 1, 1);
    launch_gemm(false, false, false, cM, cENC, cE,
                a, cE, 0, 0, W_enc, cENC, 0, 0, enc, cENC, 0, 0, b_enc, 1.f, 1, 1);
    launch_gemm(false, false, false, cM, cE, cENC,
                enc, cENC, 0, 0, W_e2d, cE, 0, 0, mem, cE, 0, 0, b_e2d, 1.f, 1, 1);

    cudaMemcpyAsync(x, labels, sizeof(float) * (size_t)cM * cE,
                    cudaMemcpyDeviceToDevice);

    for (int p = 0; p < 2; p++) {
        for (int l = 0; l < cL; l++) {
            const float* siw = sa_in_w + (size_t)l * 3 * cE * cE;
            const float* sib = sa_in_b + (size_t)l * 3 * cE;
            const float* ciw = ca_in_w + (size_t)l * 3 * cE * cE;
            const float* cib = ca_in_b + (size_t)l * 3 * cE;
            float* kvl = cakv + (size_t)l * cM * 2 * cE;

            // ===== self-attention =====
            launch_gemm(true, false, false, cM, 3 * cE, cE,
                        x, cE, 0, 0, siw, cE, 0, 0, qkv, 3 * cE, 0, 0, sib, 1.f, 1, 1);
            launch_gemm(true, false, true, cS, cS, cHD,
                        qkv,        3 * cE, sQb, cHD,
                        qkv + cE,   3 * cE, sQb, cHD,
                        sc, cS, sScb, sSch, nullptr, atscale, cB * cH, cH);
            softmax_k<<<cB * cH * cS, 256>>>(sc, cS);
            launch_gemm(false, false, false, cS, cHD, cS,
                        sc, cS, sScb, sSch,
                        qkv + 2 * cE, 3 * cE, sQb, cHD,
                        a, cE, sAb, cHD, nullptr, 1.f, cB * cH, cH);
            launch_gemm(true, false, false, cM, cE, cE,
                        a, cE, 0, 0, sa_out_w + (size_t)l * cE * cE, cE, 0, 0,
                        h, cE, 0, 0, sa_out_b + (size_t)l * cE, 1.f, 1, 1);
            add_ln_k<<<cM, 256>>>(x, h, g1 + (size_t)l * cE, be1 + (size_t)l * cE, cE);

            // ===== cross-attention (K/V cached across the two decoder passes) =====
            launch_gemm(true, false, false, cM, cE, cE,
                        x, cE, 0, 0, ciw, cE, 0, 0, qkv, 3 * cE, 0, 0, cib, 1.f, 1, 1);
            if (p == 0)
                launch_gemm(true, false, false, cM, 2 * cE, cE,
                            mem, cE, 0, 0, ciw + (size_t)cE * cE, cE, 0, 0,
                            kvl, 2 * cE, 0, 0, cib + cE, 1.f, 1, 1);
            launch_gemm(true, false, false, cS, cS, cHD,
                        qkv, 3 * cE, sQb, cHD,
                        kvl, 2 * cE, sKVb, cHD,
                        sc, cS, sScb, sSch, nullptr, atscale, cB * cH, cH);
            softmax_k<<<cB * cH * cS, 256>>>(sc, cS);
            launch_gemm(false, false, false, cS, cHD, cS,
                        sc, cS, sScb, sSch,
                        kvl + cE, 2 * cE, sKVb, cHD,
                        a, cE, sAb, cHD, nullptr, 1.f, cB * cH, cH);
            launch_gemm(true, false, false, cM, cE, cE,
                        a, cE, 0, 0, ca_out_w + (size_t)l * cE * cE, cE, 0, 0,
                        h, cE, 0, 0, ca_out_b + (size_t)l * cE, 1.f, 1, 1);
            add_ln_k<<<cM, 256>>>(x, h, g2 + (size_t)l * cE, be2 + (size_t)l * cE, cE);

            // ===== FFN (relu) — hidden reuses qkv scratch =====
            launch_gemm(true, true, false, cM, cFF, cE,
                        x, cE, 0, 0, w1 + (size_t)l * cFF * cE, cE, 0, 0,
                        qkv, cFF, 0, 0, b1 + (size_t)l * cFF, 1.f, 1, 1);
            launch_gemm(true, false, false, cM, cE, cFF,
                        qkv, cFF, 0, 0, w2 + (size_t)l * cE * cFF, cFF, 0, 0,
                        h, cE, 0, 0, b2 + (size_t)l * cE, 1.f, 1, 1);
            add_ln_k<<<cM, 256>>>(x, h, g3 + (size_t)l * cE, be3 + (size_t)l * cE, cE);
        }
        if (p == 0) {
            int total = cM * cE;
            mix_k<<<(total + 255) / 256, 256>>>(x, labels, sched, steps, total);
        }
    }

    cudaMemcpyAsync(d_out, x, sizeof(float) * (size_t)cM * cE,
                    cudaMemcpyDeviceToDevice);
}

// round 4
// speedup vs baseline: 1.8088x; 1.8088x over previous
#include <cuda_runtime.h>
#include <math.h>

// ---------------- problem constants ----------------
constexpr int cB = 16, cS = 512, cE = 768, cH = 2, cHD = 384;
constexpr int cFF = 256, cL = 3, cENC = 128, cIN = 234;
constexpr int cM = cB * cS;            // 8192 rows
constexpr float NEGBIG = -1e9f;

// ---------------- device scratch (static: no allocs allowed) ----------------
__device__ float g_x   [cM * cE];
__device__ float g_a   [cM * cE];
__device__ float g_h   [cM * cE];
__device__ float g_mem [cM * cE];
__device__ float g_enc [cM * cENC];
__device__ float g_qkv [cM * 3 * cE];
__device__ float g_sc  [cB * cH * cS * cS];
__device__ float g_cakv[cL * cM * 2 * cE];

// ---------------- GEMM: C = A * op(B) + bias ----------------
// 128x128 tile, BK=16, 256 threads, 8x8 per thread (2x2 blocks of 4x4 at
// stride 64), float4 LDS in the inner loop. M and N MUST be multiples of 128.
#define BM 128
#define BN 128
#define BKT 16

template<bool TRANSB, bool RELU, bool CAUSAL>
__global__ void __launch_bounds__(256)
gemm_k(int M, int N, int K,
       const float* __restrict__ A, int lda, long long sAo, long long sAi,
       const float* __restrict__ B, int ldb, long long sBo, long long sBi,
       float* __restrict__ C, int ldc, long long sCo, long long sCi,
       const float* __restrict__ bias, float scale, int innerH)
{
    int z  = blockIdx.z;
    int zo = z / innerH, zi = z - zo * innerH;
    A += zo * sAo + zi * sAi;
    B += zo * sBo + zi * sBi;
    C += zo * sCo + zi * sCi;

    __shared__ __align__(16) float As[BKT][BM];
    __shared__ __align__(16) float Bs[BKT][BN];

    int tid = threadIdx.x;
    int tx = tid & 15;          // column group
    int ty = tid >> 4;          // row group
    int row0 = blockIdx.y * BM;
    int col0 = blockIdx.x * BN;

    float acc[8][8];
    #pragma unroll
    for (int i = 0; i < 8; i++)
        #pragma unroll
        for (int j = 0; j < 8; j++) acc[i][j] = 0.f;

    for (int k0 = 0; k0 < K; k0 += BKT) {
        // ---- stage A tile: BM x BKT (2048 floats, 8 per thread) ----
        #pragma unroll
        for (int t = 0; t < 2; t++) {
            int slot = tid + t * 256;        // 0..511 (float4 slots)
            int r  = slot >> 2;              // 0..127
            int cq = slot & 3;               // 0..3 (k quad)
            const float* ap = A + (size_t)(row0 + r) * lda + k0 + cq * 4;
            #pragma unroll
            for (int j = 0; j < 4; j++) {
                int gk = k0 + cq * 4 + j;
                As[cq * 4 + j][r] = (gk < K) ? ap[j] : 0.f;
            }
        }
        // ---- stage B tile ----
        if (TRANSB) {
            // B is [N,K] row-major
            #pragma unroll
            for (int t = 0; t < 2; t++) {
                int slot = tid + t * 256;
                int n  = slot >> 2;
                int cq = slot & 3;
                const float* bp = B + (size_t)(col0 + n) * ldb + k0 + cq * 4;
                #pragma unroll
                for (int j = 0; j < 4; j++) {
                    int gk = k0 + cq * 4 + j;
                    Bs[cq * 4 + j][n] = (gk < K) ? bp[j] : 0.f;
                }
            }
        } else {
            // B is [K,N] row-major
            #pragma unroll
            for (int t = 0; t < 2; t++) {
                int slot = tid + t * 256;
                int kk = slot >> 5;          // 0..15
                int n4 = slot & 31;          // 0..31
                int gk = k0 + kk;
                const float* bp = B + (size_t)gk * ldb + col0 + n4 * 4;
                #pragma unroll
                for (int j = 0; j < 4; j++)
                    Bs[kk][n4 * 4 + j] = (gk < K) ? bp[j] : 0.f;
            }
        }
        __syncthreads();

        // ---- inner product: 4 x LDS.128 per 64 FFMA ----
        #pragma unroll
        for (int kk = 0; kk < BKT; kk++) {
            float4 a0 = *(const float4*)&As[kk][ty * 4];
            float4 a1 = *(const float4*)&As[kk][64 + ty * 4];
            float4 b0 = *(const float4*)&Bs[kk][tx * 4];
            float4 b1 = *(const float4*)&Bs[kk][64 + tx * 4];
            float av[8] = {a0.x, a0.y, a0.z, a0.w, a1.x, a1.y, a1.z, a1.w};
            float bv[8] = {b0.x, b0.y, b0.z, b0.w, b1.x, b1.y, b1.z, b1.w};
            #pragma unroll
            for (int i = 0; i < 8; i++)
                #pragma unroll
                for (int j = 0; j < 8; j++)
                    acc[i][j] += av[i] * bv[j];
        }
        __syncthreads();
    }

    // ---- epilogue: vectorized stores ----
    #pragma unroll
    for (int i = 0; i < 8; i++) {
        int r = row0 + ((i < 4) ? (ty * 4 + i) : (64 + ty * 4 + i - 4));
        #pragma unroll
        for (int jb = 0; jb < 2; jb++) {
            int c0 = col0 + jb * 64 + tx * 4;
            float4 v;
            float* vp = &v.x;
            #pragma unroll
            for (int j = 0; j < 4; j++) {
                float t = acc[i][jb * 4 + j] * scale;
                if (CAUSAL && (c0 + j) > r) t += NEGBIG;
                if (bias) t += bias[c0 + j];
                if (RELU) t = fmaxf(t, 0.f);
                vp[j] = t;
            }
            *(float4*)&C[(size_t)r * ldc + c0] = v;
        }
    }
}

// ---------------- block reduce helper ----------------
__device__ __forceinline__ float blockReduceSum(float v, float* s) {
    int tid = threadIdx.x;
    int nw  = blockDim.x >> 5;
    #pragma unroll
    for (int o = 16; o; o >>= 1) v += __shfl_xor_sync(0xffffffffu, v, o);
    if ((tid & 31) == 0) s[tid >> 5] = v;
    __syncthreads();
    if (tid < 32) {
        float t = (tid < nw) ? s[tid] : 0.f;
        #pragma unroll
        for (int o = 16; o; o >>= 1) t += __shfl_xor_sync(0xffffffffu, t, o);
        if (tid == 0) s[0] = t;
    }
    __syncthreads();
    float r = s[0];
    __syncthreads();
    return r;
}

// ---------------- row softmax ----------------
__global__ void softmax_k(float* __restrict__ x, int ncols) {
    x += (size_t)blockIdx.x * ncols;
    int tid = threadIdx.x;
    __shared__ float red[32];

    float mx = -3.4e38f;
    for (int i = tid; i < ncols; i += blockDim.x) mx = fmaxf(mx, x[i]);
    #pragma unroll
    for (int o = 16; o; o >>= 1) mx = fmaxf(mx, __shfl_xor_sync(0xffffffffu, mx, o));
    if ((tid & 31) == 0) red[tid >> 5] = mx;
    __syncthreads();
    if (tid < 32) {
        float t = (tid < (blockDim.x >> 5)) ? red[tid] : -3.4e38f;
        #pragma unroll
        for (int o = 16; o; o >>= 1) t = fmaxf(t, __shfl_xor_sync(0xffffffffu, t, o));
        if (tid == 0) red[0] = t;
    }
    __syncthreads();
    mx = red[0];
    __syncthreads();

    float sum = 0.f;
    for (int i = tid; i < ncols; i += blockDim.x) {
        float e = expf(x[i] - mx);
        x[i] = e;
        sum += e;
    }
    sum = blockReduceSum(sum, red);
    float inv = 1.f / sum;
    for (int i = tid; i < ncols; i += blockDim.x) x[i] *= inv;
}

// ---------------- fused x = LayerNorm(x + h) * g + b (in place) ----------------
__global__ void add_ln_k(float* __restrict__ x, const float* __restrict__ h,
                         const float* __restrict__ g, const float* __restrict__ b,
                         int ncols)
{
    size_t base = (size_t)blockIdx.x * ncols;
    int tid = threadIdx.x;
    __shared__ float red[32];

    float v[4];
    float sum = 0.f;
    int c = 0;
    for (int i = tid; i < ncols; i += blockDim.x, c++) {
        v[c] = x[base + i] + h[base + i];
        sum += v[c];
    }
    sum = blockReduceSum(sum, red);
    float mu = sum / ncols;

    float sq = 0.f;
    c = 0;
    for (int i = tid; i < ncols; i += blockDim.x, c++) {
        float d = v[c] - mu;
        sq += d * d;
    }
    sq = blockReduceSum(sq, red);
    float rstd = rsqrtf(sq / ncols + 1e-5f);

    c = 0;
    for (int i = tid; i < ncols; i += blockDim.x, c++)
        x[base + i] = (v[c] - mu) * rstd * g[i] + b[i];
}

// ---------------- scheduled sampling mix ----------------
__global__ void mix_k(float* __restrict__ x, const float* __restrict__ labels,
                      const float* __restrict__ sr, const int* __restrict__ steps,
                      int total)
{
    int i = blockIdx.x * blockDim.x + threadIdx.x;
    if (i >= total) return;
    int s = (i / cE) % cS;
    int b = i / (cE * cS);
    float thr = (float)(*steps) / 200000.0f;
    if (sr[s * cB + b] >= thr) x[i] = labels[i];
}

// ---------------- host-side gemm dispatch ----------------
static void launch_gemm(bool transB, bool relu, bool causal,
                        int M, int N, int K,
                        const float* A, int lda, long long sAo, long long sAi,
                        const float* B, int ldb, long long sBo, long long sBi,
                        float* C, int ldc, long long sCo, long long sCi,
                        const float* bias, float scale, int nz, int innerH)
{
    dim3 blk(256);
    dim3 grd(N / BN, M / BM, nz);
    if (!transB)
        gemm_k<false, false, false><<<grd, blk>>>(M, N, K, A, lda, sAo, sAi,
            B, ldb, sBo, sBi, C, ldc, sCo, sCi, bias, scale, innerH);
    else if (causal)
        gemm_k<true, false, true><<<grd, blk>>>(M, N, K, A, lda, sAo, sAi,
            B, ldb, sBo, sBi, C, ldc, sCo, sCi, bias, scale, innerH);
    else if (relu)
        gemm_k<true, true, false><<<grd, blk>>>(M, N, K, A, lda, sAo, sAi,
            B, ldb, sBo, sBi, C, ldc, sCo, sCi, bias, scale, innerH);
    else
        gemm_k<true, false, false><<<grd, blk>>>(M, N, K, A, lda, sAo, sAi,
            B, ldb, sBo, sBi, C, ldc, sCo, sCi, bias, scale, innerH);
}

extern "C" void kernel_launch(void* const* d_in, const int* in_sizes, int n_in,
                              void* d_out, int out_size)
{
    const float* batch    = (const float*)d_in[0];
    const float* labels   = (const float*)d_in[1];
    const float* sched    = (const float*)d_in[2];
    const int*   steps    = (const int*)  d_in[3];
    const float* W_pre    = (const float*)d_in[4];
    const float* b_pre    = (const float*)d_in[5];
    const float* W_enc    = (const float*)d_in[6];
    const float* b_enc    = (const float*)d_in[7];
    const float* W_e2d    = (const float*)d_in[8];
    const float* b_e2d    = (const float*)d_in[9];
    const float* sa_in_w  = (const float*)d_in[10];
    const float* sa_in_b  = (const float*)d_in[11];
    const float* sa_out_w = (const float*)d_in[12];
    const float* sa_out_b = (const float*)d_in[13];
    const float* ca_in_w  = (const float*)d_in[14];
    const float* ca_in_b  = (const float*)d_in[15];
    const float* ca_out_w = (const float*)d_in[16];
    const float* ca_out_b = (const float*)d_in[17];
    const float* w1       = (const float*)d_in[18];
    const float* b1       = (const float*)d_in[19];
    const float* w2       = (const float*)d_in[20];
    const float* b2       = (const float*)d_in[21];
    const float* g1       = (const float*)d_in[22];
    const float* be1      = (const float*)d_in[23];
    const float* g2       = (const float*)d_in[24];
    const float* be2      = (const float*)d_in[25];
    const float* g3       = (const float*)d_in[26];
    const float* be3      = (const float*)d_in[27];

    float *x, *a, *h, *mem, *enc, *qkv, *sc, *cakv;
    cudaGetSymbolAddress((void**)&x,    g_x);
    cudaGetSymbolAddress((void**)&a,    g_a);
    cudaGetSymbolAddress((void**)&h,    g_h);
    cudaGetSymbolAddress((void**)&mem,  g_mem);
    cudaGetSymbolAddress((void**)&enc,  g_enc);
    cudaGetSymbolAddress((void**)&qkv,  g_qkv);
    cudaGetSymbolAddress((void**)&sc,   g_sc);
    cudaGetSymbolAddress((void**)&cakv, g_cakv);

    const float atscale = 1.0f / sqrtf((float)cHD);
    const long long sQb  = (long long)cS * 3 * cE;
    const long long sKVb = (long long)cS * 2 * cE;
    const long long sScb = (long long)cH * cS * cS;
    const long long sSch = (long long)cS * cS;
    const long long sAb  = (long long)cS * cE;

    // ---- prenet + encoder projection chain ----
    launch_gemm(false, false, false, cM, cE, cIN,
                batch, cIN, 0, 0, W_pre, cE, 0, 0, a, cE, 0, 0, b_pre, 1.f, 1, 1);
    launch_gemm(false, false, false, cM, cENC, cE,
                a, cE, 0, 0, W_enc, cENC, 0, 0, enc, cENC, 0, 0, b_enc, 1.f, 1, 1);
    launch_gemm(false, false, false, cM, cE, cENC,
                enc, cENC, 0, 0, W_e2d, cE, 0, 0, mem, cE, 0, 0, b_e2d, 1.f, 1, 1);

    cudaMemcpyAsync(x, labels, sizeof(float) * (size_t)cM * cE,
                    cudaMemcpyDeviceToDevice);

    for (int p = 0; p < 2; p++) {
        for (int l = 0; l < cL; l++) {
            const float* siw = sa_in_w + (size_t)l * 3 * cE * cE;
            const float* sib = sa_in_b + (size_t)l * 3 * cE;
            const float* ciw = ca_in_w + (size_t)l * 3 * cE * cE;
            const float* cib = ca_in_b + (size_t)l * 3 * cE;
            float* kvl = cakv + (size_t)l * cM * 2 * cE;

            // ===== self-attention =====
            launch_gemm(true, false, false, cM, 3 * cE, cE,
                        x, cE, 0, 0, siw, cE, 0, 0, qkv, 3 * cE, 0, 0, sib, 1.f, 1, 1);
            launch_gemm(true, false, true, cS, cS, cHD,
                        qkv,        3 * cE, sQb, cHD,
                        qkv + cE,   3 * cE, sQb, cHD,
                        sc, cS, sScb, sSch, nullptr, atscale, cB * cH, cH);
            softmax_k<<<cB * cH * cS, 256>>>(sc, cS);
            launch_gemm(false, false, false, cS, cHD, cS,
                        sc, cS, sScb, sSch,
                        qkv + 2 * cE, 3 * cE, sQb, cHD,
                        a, cE, sAb, cHD, nullptr, 1.f, cB * cH, cH);
            launch_gemm(true, false, false, cM, cE, cE,
                        a, cE, 0, 0, sa_out_w + (size_t)l * cE * cE, cE, 0, 0,
                        h, cE, 0, 0, sa_out_b + (size_t)l * cE, 1.f, 1, 1);
            add_ln_k<<<cM, 256>>>(x, h, g1 + (size_t)l * cE, be1 + (size_t)l * cE, cE);

            // ===== cross-attention (K/V cached across the two decoder passes) =====
            launch_gemm(true, false, false, cM, cE, cE,
                        x, cE, 0, 0, ciw, cE, 0, 0, qkv, 3 * cE, 0, 0, cib, 1.f, 1, 1);
            if (p == 0)
                launch_gemm(true, false, false, cM, 2 * cE, cE,
                            mem, cE, 0, 0, ciw + (size_t)cE * cE, cE, 0, 0,
                            kvl, 2 * cE, 0, 0, cib + cE, 1.f, 1, 1);
            launch_gemm(true, false, false, cS, cS, cHD,
                        qkv, 3 * cE, sQb, cHD,
                        kvl, 2 * cE, sKVb, cHD,
                        sc, cS, sScb, sSch, nullptr, atscale, cB * cH, cH);
            softmax_k<<<cB * cH * cS, 256>>>(sc, cS);
            launch_gemm(false, false, false, cS, cHD, cS,
                        sc, cS, sScb, sSch,
                        kvl + cE, 2 * cE, sKVb, cHD,
                        a, cE, sAb, cHD, nullptr, 1.f, cB * cH, cH);
            launch_gemm(true, false, false, cM, cE, cE,
                        a, cE, 0, 0, ca_out_w + (size_t)l * cE * cE, cE, 0, 0,
                        h, cE, 0, 0, ca_out_b + (size_t)l * cE, 1.f, 1, 1);
            add_ln_k<<<cM, 256>>>(x, h, g2 + (size_t)l * cE, be2 + (size_t)l * cE, cE);

            // ===== FFN (relu) — hidden reuses qkv scratch =====
            launch_gemm(true, true, false, cM, cFF, cE,
                        x, cE, 0, 0, w1 + (size_t)l * cFF * cE, cE, 0, 0,
                        qkv, cFF, 0, 0, b1 + (size_t)l * cFF, 1.f, 1, 1);
            launch_gemm(true, false, false, cM, cE, cFF,
                        qkv, cFF, 0, 0, w2 + (size_t)l * cE * cFF, cFF, 0, 0,
                        h, cE, 0, 0, b2 + (size_t)l * cE, 1.f, 1, 1);
            add_ln_k<<<cM, 256>>>(x, h, g3 + (size_t)l * cE, be3 + (size_t)l * cE, cE);
        }
        if (p == 0) {
            int total = cM * cE;
            mix_k<<<(total + 255) / 256, 256>>>(x, labels, sched, steps, total);
        }
    }

    cudaMemcpyAsync(d_out, x, sizeof(float) * (size_t)cM * cE,
                    cudaMemcpyDeviceToDevice);
}

// round 7
// speedup vs baseline: 2.8740x; 1.5889x over previous
#include <cuda_runtime.h>
#include <math.h>
#include <stdint.h>

// ---------------- problem constants ----------------
constexpr int cB = 16, cS = 512, cE = 768, cH = 2, cHD = 384;
constexpr int cFF = 256, cL = 3, cENC = 128, cIN = 234;
constexpr int cM = cB * cS;            // 8192 rows
constexpr float NEGBIG = -1e9f;

// ---------------- device scratch (static: no allocs allowed) ----------------
__device__ float g_x   [cM * cE];
__device__ float g_a   [cM * cE];
__device__ float g_h   [cM * cE];
__device__ float g_mem [cM * cE];
__device__ float g_enc [cM * cENC];
__device__ float g_qkv [cM * 3 * cE];
__device__ float g_sc  [cB * cH * cS * cS];
__device__ float g_cakv[cL * cM * 2 * cE];

// ================= tf32 mma.sync GEMM (base PTX, no tcgen05) =================
// C = A * op(B). 128x128 CTA tile, 256 thr, 8 warps (2x4), warp tile 64x32.
// fp32 inputs split in registers: x = hi(tf32) + lo(tf32);
// D += Ah*Bh + Ah*Bl + Al*Bh  (~21-bit effective mantissa).
// M, N multiples of 128; K multiple of 32.

constexpr int TBK  = 32;               // k per chunk (floats)
constexpr int TBKP = 36;               // padded smem row stride (floats)
constexpr int TILE_FLOATS = 128 * TBKP;          // 4608
constexpr int TBUF_FLOATS = 2 * TILE_FLOATS;     // A + B
constexpr int TSMEM_BYTES = 2 * TBUF_FLOATS * 4; // double buffered = 73728

__device__ __forceinline__ uint32_t smem_u32(const void* p) {
    uint32_t a;
    asm("{ .reg .u64 t; cvta.to.shared.u64 t, %1; cvt.u32.u64 %0, t; }"
        : "=r"(a) : "l"(p));
    return a;
}
__device__ __forceinline__ uint32_t tf32r(float x) {
    uint32_t u;
    asm("cvt.rna.tf32.f32 %0, %1;" : "=r"(u) : "f"(x));
    return u;
}
__device__ __forceinline__ void cp_async16(uint32_t saddr, const void* g) {
    asm volatile("cp.async.ca.shared.global [%0], [%1], 16;"
                 :: "r"(saddr), "l"(g) : "memory");
}
__device__ __forceinline__ void mma8(float* d, const uint32_t* a, const uint32_t* b) {
    asm volatile(
        "mma.sync.aligned.m16n8k8.row.col.f32.tf32.tf32.f32 "
        "{%0,%1,%2,%3}, {%4,%5,%6,%7}, {%8,%9}, {%0,%1,%2,%3};"
        : "+f"(d[0]), "+f"(d[1]), "+f"(d[2]), "+f"(d[3])
        : "r"(a[0]), "r"(a[1]), "r"(a[2]), "r"(a[3]), "r"(b[0]), "r"(b[1]));
}

// stage one chunk: A[128 x 32] (cp.async), B depends on layout.
// smem layout: row-major [rowIdx][k] with stride TBKP. TN: B rows = n (cp.async).
// NN: B rows = n but gmem is [k][n] -> LDG float4 along n + scatter STS.
template<bool TRANSB>
__device__ __forceinline__ void stage_tiles(
    const float* __restrict__ A, int lda,
    const float* __restrict__ B, int ldb,
    int row0, int col0, int k0,
    float* __restrict__ Bbuf, uint32_t sAb, uint32_t sBb, int tid)
{
    #pragma unroll
    for (int t = 0; t < 4; t++) {
        int slot = tid + t * 256;
        int r = slot >> 3, kq = slot & 7;
        cp_async16(sAb + (uint32_t)(r * TBKP + kq * 4) * 4u,
                   A + (size_t)(row0 + r) * lda + k0 + kq * 4);
    }
    if (TRANSB) {
        #pragma unroll
        for (int t = 0; t < 4; t++) {
            int slot = tid + t * 256;
            int n = slot >> 3, kq = slot & 7;
            cp_async16(sBb + (uint32_t)(n * TBKP + kq * 4) * 4u,
                       B + (size_t)(col0 + n) * ldb + k0 + kq * 4);
        }
    } else {
        #pragma unroll
        for (int t = 0; t < 4; t++) {
            int slot = tid + t * 256;
            int k = slot >> 5, n4 = slot & 31;
            float4 v = *(const float4*)(B + (size_t)(k0 + k) * ldb + col0 + n4 * 4);
            Bbuf[(n4 * 4 + 0) * TBKP + k] = v.x;
            Bbuf[(n4 * 4 + 1) * TBKP + k] = v.y;
            Bbuf[(n4 * 4 + 2) * TBKP + k] = v.z;
            Bbuf[(n4 * 4 + 3) * TBKP + k] = v.w;
        }
    }
    asm volatile("cp.async.commit_group;" ::: "memory");
}

template<bool TRANSB, bool RELU, bool CAUSAL>
__global__ void __launch_bounds__(256)
tmma_k(int M, int N, int K,
       const float* __restrict__ A, int lda, long long sAo, long long sAi,
       const float* __restrict__ B, int ldb, long long sBo, long long sBi,
       float* __restrict__ C, int ldc, long long sCo, long long sCi,
       const float* __restrict__ bias, float scale, int innerH)
{
    extern __shared__ float ts[];
    int z  = blockIdx.z;
    int zo = z / innerH, zi = z - zo * innerH;
    A += zo * sAo + zi * sAi;
    B += zo * sBo + zi * sBi;
    C += zo * sCo + zi * sCi;

    const int tid = threadIdx.x;
    const int lane = tid & 31;
    const int wid  = tid >> 5;
    const int wm = wid >> 2;           // 0..1
    const int wn = wid & 3;            // 0..3
    const int row0 = blockIdx.y * 128;
    const int col0 = blockIdx.x * 128;

    const uint32_t sb = smem_u32(ts);

    float acc[4][4][4];
    #pragma unroll
    for (int i = 0; i < 4; i++)
        #pragma unroll
        for (int j = 0; j < 4; j++)
            #pragma unroll
            for (int q = 0; q < 4; q++) acc[i][j][q] = 0.f;

    const int nch = K / TBK;
    const int lr = lane >> 2;          // 0..7
    const int lc = lane & 3;           // 0..3

    // prologue: stage chunk 0 into buf 0
    stage_tiles<TRANSB>(A, lda, B, ldb, row0, col0, 0,
                        ts + TILE_FLOATS, sb, sb + TILE_FLOATS * 4, tid);

    for (int c = 0; c < nch; c++) {
        int buf = c & 1;
        if (c + 1 < nch) {
            int nb = buf ^ 1;
            stage_tiles<TRANSB>(A, lda, B, ldb, row0, col0, (c + 1) * TBK,
                                ts + nb * TBUF_FLOATS + TILE_FLOATS,
                                sb + (uint32_t)(nb * TBUF_FLOATS) * 4u,
                                sb + (uint32_t)(nb * TBUF_FLOATS + TILE_FLOATS) * 4u,
                                tid);
            asm volatile("cp.async.wait_group 1;" ::: "memory");
        } else {
            asm volatile("cp.async.wait_group 0;" ::: "memory");
        }
        __syncthreads();

        const float* Abuf = ts + buf * TBUF_FLOATS;
        const float* Bbuf = Abuf + TILE_FLOATS;

        #pragma unroll
        for (int kk = 0; kk < TBK; kk += 8) {
            // B fragments (4 n-tiles), split hi/lo
            uint32_t bh[4][2], bl[4][2];
            #pragma unroll
            for (int nt = 0; nt < 4; nt++) {
                #pragma unroll
                for (int j = 0; j < 2; j++) {
                    float v = Bbuf[(wn * 32 + nt * 8 + lr) * TBKP + kk + lc + 4 * j];
                    uint32_t h = tf32r(v);
                    bh[nt][j] = h;
                    bl[nt][j] = tf32r(v - __uint_as_float(h));
                }
            }
            #pragma unroll
            for (int mt = 0; mt < 4; mt++) {
                uint32_t ah[4], al[4];
                #pragma unroll
                for (int i = 0; i < 4; i++) {
                    int r  = wm * 64 + mt * 16 + lr + (i & 1) * 8;
                    int kc = kk + lc + (i >> 1) * 4;
                    float v = Abuf[r * TBKP + kc];
                    ah[i] = tf32r(v);
                    al[i] = tf32r(v - __uint_as_float(ah[i]));
                }
                #pragma unroll
                for (int nt = 0; nt < 4; nt++) {
                    mma8(acc[mt][nt], ah, bh[nt]);
                    mma8(acc[mt][nt], ah, bl[nt]);
                    mma8(acc[mt][nt], al, bh[nt]);
                }
            }
        }
        __syncthreads();
    }

    // ---- epilogue ----
    #pragma unroll
    for (int mt = 0; mt < 4; mt++) {
        int rb = row0 + wm * 64 + mt * 16 + lr;
        #pragma unroll
        for (int nt = 0; nt < 4; nt++) {
            int cc = col0 + wn * 32 + nt * 8 + 2 * lc;
            #pragma unroll
            for (int half = 0; half < 2; half++) {
                int r = rb + half * 8;
                float v0 = acc[mt][nt][half * 2 + 0] * scale;
                float v1 = acc[mt][nt][half * 2 + 1] * scale;
                if (CAUSAL) {
                    if (cc > r)     v0 += NEGBIG;
                    if (cc + 1 > r) v1 += NEGBIG;
                }
                if (bias) { v0 += bias[cc]; v1 += bias[cc + 1]; }
                if (RELU) { v0 = fmaxf(v0, 0.f); v1 = fmaxf(v1, 0.f); }
                *(float2*)&C[(size_t)r * ldc + cc] = make_float2(v0, v1);
            }
        }
    }
}

// ================= SIMT GEMM (prenet only: K=234) =============
#define BM 128
#define BN 128
#define BKT 16

__global__ void __launch_bounds__(256)
gemm_nn_k(int M, int N, int K,
          const float* __restrict__ A, int lda,
          const float* __restrict__ B, int ldb,
          float* __restrict__ C, int ldc,
          const float* __restrict__ bias)
{
    __shared__ __align__(16) float As[BKT][BM];
    __shared__ __align__(16) float Bs[BKT][BN];

    int tid = threadIdx.x;
    int tx = tid & 15;
    int ty = tid >> 4;
    int row0 = blockIdx.y * BM;
    int col0 = blockIdx.x * BN;

    float acc[8][8];
    #pragma unroll
    for (int i = 0; i < 8; i++)
        #pragma unroll
        for (int j = 0; j < 8; j++) acc[i][j] = 0.f;

    for (int k0 = 0; k0 < K; k0 += BKT) {
        #pragma unroll
        for (int t = 0; t < 2; t++) {
            int slot = tid + t * 256;
            int r  = slot >> 2;
            int cq = slot & 3;
            const float* ap = A + (size_t)(row0 + r) * lda + k0 + cq * 4;
            #pragma unroll
            for (int j = 0; j < 4; j++) {
                int gk = k0 + cq * 4 + j;
                As[cq * 4 + j][r] = (gk < K) ? ap[j] : 0.f;
            }
        }
        #pragma unroll
        for (int t = 0; t < 2; t++) {
            int slot = tid + t * 256;
            int kk = slot >> 5;
            int n4 = slot & 31;
            int gk = k0 + kk;
            const float* bp = B + (size_t)gk * ldb + col0 + n4 * 4;
            #pragma unroll
            for (int j = 0; j < 4; j++)
                Bs[kk][n4 * 4 + j] = (gk < K) ? bp[j] : 0.f;
        }
        __syncthreads();

        #pragma unroll
        for (int kk = 0; kk < BKT; kk++) {
            float4 a0 = *(const float4*)&As[kk][ty * 4];
            float4 a1 = *(const float4*)&As[kk][64 + ty * 4];
            float4 b0 = *(const float4*)&Bs[kk][tx * 4];
            float4 b1 = *(const float4*)&Bs[kk][64 + tx * 4];
            float av[8] = {a0.x, a0.y, a0.z, a0.w, a1.x, a1.y, a1.z, a1.w};
            float bv[8] = {b0.x, b0.y, b0.z, b0.w, b1.x, b1.y, b1.z, b1.w};
            #pragma unroll
            for (int i = 0; i < 8; i++)
                #pragma unroll
                for (int j = 0; j < 8; j++)
                    acc[i][j] += av[i] * bv[j];
        }
        __syncthreads();
    }

    #pragma unroll
    for (int i = 0; i < 8; i++) {
        int r = row0 + ((i < 4) ? (ty * 4 + i) : (64 + ty * 4 + i - 4));
        #pragma unroll
        for (int jb = 0; jb < 2; jb++) {
            int c0 = col0 + jb * 64 + tx * 4;
            float4 v;
            float* vp = &v.x;
            #pragma unroll
            for (int j = 0; j < 4; j++)
                vp[j] = acc[i][jb * 4 + j] + bias[c0 + j];
            *(float4*)&C[(size_t)r * ldc + c0] = v;
        }
    }
}

// ---------------- block reduce helper ----------------
__device__ __forceinline__ float blockReduceSum(float v, float* s) {
    int tid = threadIdx.x;
    int nw  = blockDim.x >> 5;
    #pragma unroll
    for (int o = 16; o; o >>= 1) v += __shfl_xor_sync(0xffffffffu, v, o);
    if ((tid & 31) == 0) s[tid >> 5] = v;
    __syncthreads();
    if (tid < 32) {
        float t = (tid < nw) ? s[tid] : 0.f;
        #pragma unroll
        for (int o = 16; o; o >>= 1) t += __shfl_xor_sync(0xffffffffu, t, o);
        if (tid == 0) s[0] = t;
    }
    __syncthreads();
    float r = s[0];
    __syncthreads();
    return r;
}

// ---------------- row softmax ----------------
__global__ void softmax_k(float* __restrict__ x, int ncols) {
    x += (size_t)blockIdx.x * ncols;
    int tid = threadIdx.x;
    __shared__ float red[32];

    float mx = -3.4e38f;
    for (int i = tid; i < ncols; i += blockDim.x) mx = fmaxf(mx, x[i]);
    #pragma unroll
    for (int o = 16; o; o >>= 1) mx = fmaxf(mx, __shfl_xor_sync(0xffffffffu, mx, o));
    if ((tid & 31) == 0) red[tid >> 5] = mx;
    __syncthreads();
    if (tid < 32) {
        float t = (tid < (blockDim.x >> 5)) ? red[tid] : -3.4e38f;
        #pragma unroll
        for (int o = 16; o; o >>= 1) t = fmaxf(t, __shfl_xor_sync(0xffffffffu, t, o));
        if (tid == 0) red[0] = t;
    }
    __syncthreads();
    mx = red[0];
    __syncthreads();

    float sum = 0.f;
    for (int i = tid; i < ncols; i += blockDim.x) {
        float e = expf(x[i] - mx);
        x[i] = e;
        sum += e;
    }
    sum = blockReduceSum(sum, red);
    float inv = 1.f / sum;
    for (int i = tid; i < ncols; i += blockDim.x) x[i] *= inv;
}

// ---------------- fused x = LayerNorm(x + h) * g + b (in place) ----------------
__global__ void add_ln_k(float* __restrict__ x, const float* __restrict__ h,
                         const float* __restrict__ g, const float* __restrict__ b,
                         int ncols)
{
    size_t base = (size_t)blockIdx.x * ncols;
    int tid = threadIdx.x;
    __shared__ float red[32];

    float v[4];
    float sum = 0.f;
    int c = 0;
    for (int i = tid; i < ncols; i += blockDim.x, c++) {
        v[c] = x[base + i] + h[base + i];
        sum += v[c];
    }
    sum = blockReduceSum(sum, red);
    float mu = sum / ncols;

    float sq = 0.f;
    c = 0;
    for (int i = tid; i < ncols; i += blockDim.x, c++) {
        float d = v[c] - mu;
        sq += d * d;
    }
    sq = blockReduceSum(sq, red);
    float rstd = rsqrtf(sq / ncols + 1e-5f);

    c = 0;
    for (int i = tid; i < ncols; i += blockDim.x, c++)
        x[base + i] = (v[c] - mu) * rstd * g[i] + b[i];
}

// ---------------- scheduled sampling mix ----------------
__global__ void mix_k(float* __restrict__ x, const float* __restrict__ labels,
                      const float* __restrict__ sr, const int* __restrict__ steps,
                      int total)
{
    int i = blockIdx.x * blockDim.x + threadIdx.x;
    if (i >= total) return;
    int s = (i / cE) % cS;
    int b = i / (cE * cS);
    float thr = (float)(*steps) / 200000.0f;
    if (sr[s * cB + b] >= thr) x[i] = labels[i];
}

// ---------------- host-side dispatch ----------------
static void launch_tmma(bool transB, bool relu, bool causal,
                        int M, int N, int K,
                        const float* A, int lda, long long sAo, long long sAi,
                        const float* B, int ldb, long long sBo, long long sBi,
                        float* C, int ldc, long long sCo, long long sCi,
                        const float* bias, float scale, int nz, int innerH)
{
    dim3 blk(256);
    dim3 grd(N / 128, M / 128, nz);
    if (!transB) {
        cudaFuncSetAttribute((const void*)tmma_k<false, false, false>,
                             cudaFuncAttributeMaxDynamicSharedMemorySize, TSMEM_BYTES);
        tmma_k<false, false, false><<<grd, blk, TSMEM_BYTES>>>(M, N, K, A, lda, sAo, sAi,
            B, ldb, sBo, sBi, C, ldc, sCo, sCi, bias, scale, innerH);
    } else if (causal) {
        cudaFuncSetAttribute((const void*)tmma_k<true, false, true>,
                             cudaFuncAttributeMaxDynamicSharedMemorySize, TSMEM_BYTES);
        tmma_k<true, false, true><<<grd, blk, TSMEM_BYTES>>>(M, N, K, A, lda, sAo, sAi,
            B, ldb, sBo, sBi, C, ldc, sCo, sCi, bias, scale, innerH);
    } else if (relu) {
        cudaFuncSetAttribute((const void*)tmma_k<true, true, false>,
                             cudaFuncAttributeMaxDynamicSharedMemorySize, TSMEM_BYTES);
        tmma_k<true, true, false><<<grd, blk, TSMEM_BYTES>>>(M, N, K, A, lda, sAo, sAi,
            B, ldb, sBo, sBi, C, ldc, sCo, sCi, bias, scale, innerH);
    } else {
        cudaFuncSetAttribute((const void*)tmma_k<true, false, false>,
                             cudaFuncAttributeMaxDynamicSharedMemorySize, TSMEM_BYTES);
        tmma_k<true, false, false><<<grd, blk, TSMEM_BYTES>>>(M, N, K, A, lda, sAo, sAi,
            B, ldb, sBo, sBi, C, ldc, sCo, sCi, bias, scale, innerH);
    }
}

extern "C" void kernel_launch(void* const* d_in, const int* in_sizes, int n_in,
                              void* d_out, int out_size)
{
    const float* batch    = (const float*)d_in[0];
    const float* labels   = (const float*)d_in[1];
    const float* sched    = (const float*)d_in[2];
    const int*   steps    = (const int*)  d_in[3];
    const float* W_pre    = (const float*)d_in[4];
    const float* b_pre    = (const float*)d_in[5];
    const float* W_enc    = (const float*)d_in[6];
    const float* b_enc    = (const float*)d_in[7];
    const float* W_e2d    = (const float*)d_in[8];
    const float* b_e2d    = (const float*)d_in[9];
    const float* sa_in_w  = (const float*)d_in[10];
    const float* sa_in_b  = (const float*)d_in[11];
    const float* sa_out_w = (const float*)d_in[12];
    const float* sa_out_b = (const float*)d_in[13];
    const float* ca_in_w  = (const float*)d_in[14];
    const float* ca_in_b  = (const float*)d_in[15];
    const float* ca_out_w = (const float*)d_in[16];
    const float* ca_out_b = (const float*)d_in[17];
    const float* w1       = (const float*)d_in[18];
    const float* b1       = (const float*)d_in[19];
    const float* w2       = (const float*)d_in[20];
    const float* b2       = (const float*)d_in[21];
    const float* g1       = (const float*)d_in[22];
    const float* be1      = (const float*)d_in[23];
    const float* g2       = (const float*)d_in[24];
    const float* be2      = (const float*)d_in[25];
    const float* g3       = (const float*)d_in[26];
    const float* be3      = (const float*)d_in[27];

    float *x, *a, *h, *mem, *enc, *qkv, *sc, *cakv;
    cudaGetSymbolAddress((void**)&x,    g_x);
    cudaGetSymbolAddress((void**)&a,    g_a);
    cudaGetSymbolAddress((void**)&h,    g_h);
    cudaGetSymbolAddress((void**)&mem,  g_mem);
    cudaGetSymbolAddress((void**)&enc,  g_enc);
    cudaGetSymbolAddress((void**)&qkv,  g_qkv);
    cudaGetSymbolAddress((void**)&sc,   g_sc);
    cudaGetSymbolAddress((void**)&cakv, g_cakv);

    const float atscale = 1.0f / sqrtf((float)cHD);
    const long long sQb  = (long long)cS * 3 * cE;
    const long long sKVb = (long long)cS * 2 * cE;
    const long long sScb = (long long)cH * cS * cS;
    const long long sSch = (long long)cS * cS;
    const long long sAb  = (long long)cS * cE;

    // ---- prenet (K=234: SIMT) + encoder chain (NN tensor) ----
    {
        dim3 blk(256), grd(cE / BN, cM / BM, 1);
        gemm_nn_k<<<grd, blk>>>(cM, cE, cIN, batch, cIN, W_pre, cE, a, cE, b_pre);
    }
    launch_tmma(false, false, false, cM, cENC, cE,
                a, cE, 0, 0, W_enc, cENC, 0, 0, enc, cENC, 0, 0, b_enc, 1.f, 1, 1);
    launch_tmma(false, false, false, cM, cE, cENC,
                enc, cENC, 0, 0, W_e2d, cE, 0, 0, mem, cE, 0, 0, b_e2d, 1.f, 1, 1);

    cudaMemcpyAsync(x, labels, sizeof(float) * (size_t)cM * cE,
                    cudaMemcpyDeviceToDevice);

    for (int p = 0; p < 2; p++) {
        for (int l = 0; l < cL; l++) {
            const float* siw = sa_in_w + (size_t)l * 3 * cE * cE;
            const float* sib = sa_in_b + (size_t)l * 3 * cE;
            const float* ciw = ca_in_w + (size_t)l * 3 * cE * cE;
            const float* cib = ca_in_b + (size_t)l * 3 * cE;
            float* kvl = cakv + (size_t)l * cM * 2 * cE;

            // ===== self-attention =====
            launch_tmma(true, false, false, cM, 3 * cE, cE,
                        x, cE, 0, 0, siw, cE, 0, 0, qkv, 3 * cE, 0, 0, sib, 1.f, 1, 1);
            launch_tmma(true, false, true, cS, cS, cHD,
                        qkv,        3 * cE, sQb, cHD,
                        qkv + cE,   3 * cE, sQb, cHD,
                        sc, cS, sScb, sSch, nullptr, atscale, cB * cH, cH);
            softmax_k<<<cB * cH * cS, 256>>>(sc, cS);
            launch_tmma(false, false, false, cS, cHD, cS,
                        sc, cS, sScb, sSch,
                        qkv + 2 * cE, 3 * cE, sQb, cHD,
                        a, cE, sAb, cHD, nullptr, 1.f, cB * cH, cH);
            launch_tmma(true, false, false, cM, cE, cE,
                        a, cE, 0, 0, sa_out_w + (size_t)l * cE * cE, cE, 0, 0,
                        h, cE, 0, 0, sa_out_b + (size_t)l * cE, 1.f, 1, 1);
            add_ln_k<<<cM, 256>>>(x, h, g1 + (size_t)l * cE, be1 + (size_t)l * cE, cE);

            // ===== cross-attention (K/V cached across the two decoder passes) =====
            launch_tmma(true, false, false, cM, cE, cE,
                        x, cE, 0, 0, ciw, cE, 0, 0, qkv, 3 * cE, 0, 0, cib, 1.f, 1, 1);
            if (p == 0)
                launch_tmma(true, false, false, cM, 2 * cE, cE,
                            mem, cE, 0, 0, ciw + (size_t)cE * cE, cE, 0, 0,
                            kvl, 2 * cE, 0, 0, cib + cE, 1.f, 1, 1);
            launch_tmma(true, false, false, cS, cS, cHD,
                        qkv, 3 * cE, sQb, cHD,
                        kvl, 2 * cE, sKVb, cHD,
                        sc, cS, sScb, sSch, nullptr, atscale, cB * cH, cH);
            softmax_k<<<cB * cH * cS, 256>>>(sc, cS);
            launch_tmma(false, false, false, cS, cHD, cS,
                        sc, cS, sScb, sSch,
                        kvl + cE, 2 * cE, sKVb, cHD,
                        a, cE, sAb, cHD, nullptr, 1.f, cB * cH, cH);
            launch_tmma(true, false, false, cM, cE, cE,
                        a, cE, 0, 0, ca_out_w + (size_t)l * cE * cE, cE, 0, 0,
                        h, cE, 0, 0, ca_out_b + (size_t)l * cE, 1.f, 1, 1);
            add_ln_k<<<cM, 256>>>(x, h, g2 + (size_t)l * cE, be2 + (size_t)l * cE, cE);

            // ===== FFN (relu) — hidden reuses qkv scratch =====
            launch_tmma(true, true, false, cM, cFF, cE,
                        x, cE, 0, 0, w1 + (size_t)l * cFF * cE, cE, 0, 0,
                        qkv, cFF, 0, 0, b1 + (size_t)l * cFF, 1.f, 1, 1);
            launch_tmma(true, false, false, cM, cE, cFF,
                        qkv, cFF, 0, 0, w2 + (size_t)l * cE * cFF, cFF, 0, 0,
                        h, cE, 0, 0, b2 + (size_t)l * cE, 1.f, 1, 1);
            add_ln_k<<<cM, 256>>>(x, h, g3 + (size_t)l * cE, be3 + (size_t)l * cE, cE);
        }
        if (p == 0) {
            int total = cM * cE;
            mix_k<<<(total + 255) / 256, 256>>>(x, labels, sched, steps, total);
        }
    }

    cudaMemcpyAsync(d_out, x, sizeof(float) * (size_t)cM * cE,
                    cudaMemcpyDeviceToDevice);
}

// round 8
// speedup vs baseline: 4.4209x; 1.5383x over previous
#include <cuda_runtime.h>
#include <cuda_bf16.h>
#include <math.h>
#include <stdint.h>

// ---------------- problem constants ----------------
constexpr int cB = 16, cS = 512, cE = 768, cH = 2, cHD = 384;
constexpr int cFF = 256, cL = 3, cENC = 128, cIN = 234;
constexpr int cM = cB * cS;            // 8192 rows
constexpr float NEGBIG = -1e9f;

// ---------------- device scratch (static: no allocs allowed) ----------------
__device__ float g_x   [cM * cE];
__device__ float g_a   [cM * cE];
__device__ float g_h   [cM * cE];
__device__ float g_mem [cM * cE];
__device__ float g_enc [cM * cENC];
__device__ float g_qkv [cM * 3 * cE];
__device__ float g_sc  [cB * cH * cS * cS];
__device__ float g_cakv[cL * cM * 2 * cE];

// ============ bf16 split mma.sync GEMM (base PTX, m16n8k16) =================
// C = A * op(B). 128x128 CTA tile, 256 thr, 8 warps (2x4), warp tile 64x32.
// fp32 split at staging: x = hi(bf16) + lo(bf16) stored in separate smem
// planes; D += Ah*Bh + Ah*Bl + Al*Bh  (~16-bit effective mantissa).
// M, N multiples of 128; K multiple of 32.

constexpr int TBK = 32;                 // k floats per chunk
constexpr int PSU = 20;                 // plane row stride in u32 (40 bf16) - bank-conflict-free
constexpr int PLANE_U32 = 128 * PSU;    // 2560 u32 = 10240 B per plane
// planes: Ahi, Alo, Bhi, Blo
constexpr int TSMEM_BYTES = 4 * PLANE_U32 * 4;   // 40960

__device__ __forceinline__ void mma16(float* d, const uint32_t* a, const uint32_t* b) {
    asm volatile(
        "mma.sync.aligned.m16n8k16.row.col.f32.bf16.bf16.f32 "
        "{%0,%1,%2,%3}, {%4,%5,%6,%7}, {%8,%9}, {%0,%1,%2,%3};"
        : "+f"(d[0]), "+f"(d[1]), "+f"(d[2]), "+f"(d[3])
        : "r"(a[0]), "r"(a[1]), "r"(a[2]), "r"(a[3]), "r"(b[0]), "r"(b[1]));
}

// convert float4 (4 consecutive k) -> hi/lo bf16 pairs, store 8B to each plane
__device__ __forceinline__ void cvt_split_sts(uint32_t* __restrict__ hi,
                                              uint32_t* __restrict__ lo,
                                              int r, int kq, float4 v) {
    __nv_bfloat162 h01 = __floats2bfloat162_rn(v.x, v.y);
    __nv_bfloat162 h23 = __floats2bfloat162_rn(v.z, v.w);
    float lx = v.x - __bfloat162float(h01.x);
    float ly = v.y - __bfloat162float(h01.y);
    float lz = v.z - __bfloat162float(h23.x);
    float lw = v.w - __bfloat162float(h23.y);
    __nv_bfloat162 l01 = __floats2bfloat162_rn(lx, ly);
    __nv_bfloat162 l23 = __floats2bfloat162_rn(lz, lw);
    int idx = r * PSU + kq * 2;
    uint2 hv, lv;
    hv.x = *(uint32_t*)&h01; hv.y = *(uint32_t*)&h23;
    lv.x = *(uint32_t*)&l01; lv.y = *(uint32_t*)&l23;
    *(uint2*)&hi[idx] = hv;
    *(uint2*)&lo[idx] = lv;
}

template<bool TRANSB>
__device__ __forceinline__ void load_regs(
    float4* pA, float4* pB,
    const float* __restrict__ A, int lda,
    const float* __restrict__ B, int ldb,
    int row0, int col0, int k0, int tid)
{
    #pragma unroll
    for (int t = 0; t < 4; t++) {
        int slot = tid + t * 256;
        int r = slot >> 3, kq = slot & 7;
        pA[t] = *(const float4*)(A + (size_t)(row0 + r) * lda + k0 + kq * 4);
    }
    if (TRANSB) {
        #pragma unroll
        for (int t = 0; t < 4; t++) {
            int slot = tid + t * 256;
            int n = slot >> 3, kq = slot & 7;
            pB[t] = *(const float4*)(B + (size_t)(col0 + n) * ldb + k0 + kq * 4);
        }
    } else {
        #pragma unroll
        for (int t = 0; t < 4; t++) {
            int slot = tid + t * 256;
            int k = slot >> 5, n4 = slot & 31;
            pB[t] = *(const float4*)(B + (size_t)(k0 + k) * ldb + col0 + n4 * 4);
        }
    }
}

template<bool TRANSB, bool RELU, bool CAUSAL>
__global__ void __launch_bounds__(256)
tmma_k(int M, int N, int K,
       const float* __restrict__ A, int lda, long long sAo, long long sAi,
       const float* __restrict__ B, int ldb, long long sBo, long long sBi,
       float* __restrict__ C, int ldc, long long sCo, long long sCi,
       const float* __restrict__ bias, float scale, int innerH)
{
    extern __shared__ uint32_t ts[];
    int z  = blockIdx.z;
    int zo = z / innerH, zi = z - zo * innerH;
    A += zo * sAo + zi * sAi;
    B += zo * sBo + zi * sBi;
    C += zo * sCo + zi * sCi;

    uint32_t* Ahi = ts;
    uint32_t* Alo = ts + PLANE_U32;
    uint32_t* Bhi = ts + 2 * PLANE_U32;
    uint32_t* Blo = ts + 3 * PLANE_U32;

    const int tid = threadIdx.x;
    const int lane = tid & 31;
    const int wid  = tid >> 5;
    const int wm = wid >> 2;           // 0..1
    const int wn = wid & 3;            // 0..3
    const int row0 = blockIdx.y * 128;
    const int col0 = blockIdx.x * 128;
    const int lr = lane >> 2;          // 0..7
    const int lc = lane & 3;           // 0..3

    float acc[4][4][4];
    #pragma unroll
    for (int i = 0; i < 4; i++)
        #pragma unroll
        for (int j = 0; j < 4; j++)
            #pragma unroll
            for (int q = 0; q < 4; q++) acc[i][j][q] = 0.f;

    const int nch = K / TBK;
    float4 pA[4], pB[4];
    load_regs<TRANSB>(pA, pB, A, lda, B, ldb, row0, col0, 0, tid);

    for (int c = 0; c < nch; c++) {
        // ---- convert + store current chunk ----
        #pragma unroll
        for (int t = 0; t < 4; t++) {
            int slot = tid + t * 256;
            int r = slot >> 3, kq = slot & 7;
            cvt_split_sts(Ahi, Alo, r, kq, pA[t]);
        }
        if (TRANSB) {
            #pragma unroll
            for (int t = 0; t < 4; t++) {
                int slot = tid + t * 256;
                int n = slot >> 3, kq = slot & 7;
                cvt_split_sts(Bhi, Blo, n, kq, pB[t]);
            }
        } else {
            __nv_bfloat16* bh16 = (__nv_bfloat16*)Bhi;
            __nv_bfloat16* bl16 = (__nv_bfloat16*)Blo;
            #pragma unroll
            for (int t = 0; t < 4; t++) {
                int slot = tid + t * 256;
                int k = slot >> 5, n4 = slot & 31;
                const float* vv = &pB[t].x;
                #pragma unroll
                for (int j = 0; j < 4; j++) {
                    int n = n4 * 4 + j;
                    __nv_bfloat16 hb = __float2bfloat16_rn(vv[j]);
                    float lf = vv[j] - __bfloat162float(hb);
                    bh16[n * (2 * PSU) + k] = hb;
                    bl16[n * (2 * PSU) + k] = __float2bfloat16_rn(lf);
                }
            }
        }
        // prefetch next chunk (LDG overlaps MMA phase)
        if (c + 1 < nch)
            load_regs<TRANSB>(pA, pB, A, lda, B, ldb, row0, col0, (c + 1) * TBK, tid);
        __syncthreads();

        // ---- MMA phase: 2 k-steps of 16 ----
        #pragma unroll
        for (int ks = 0; ks < 2; ks++) {
            int kb = ks * 8 + lc;
            uint32_t bh[4][2], bl[4][2];
            #pragma unroll
            for (int nt = 0; nt < 4; nt++) {
                int n = wn * 32 + nt * 8 + lr;
                bh[nt][0] = Bhi[n * PSU + kb];
                bh[nt][1] = Bhi[n * PSU + kb + 4];
                bl[nt][0] = Blo[n * PSU + kb];
                bl[nt][1] = Blo[n * PSU + kb + 4];
            }
            #pragma unroll
            for (int mt = 0; mt < 4; mt++) {
                int r = wm * 64 + mt * 16 + lr;
                uint32_t ah[4], al[4];
                ah[0] = Ahi[r * PSU + kb];
                ah[1] = Ahi[(r + 8) * PSU + kb];
                ah[2] = Ahi[r * PSU + kb + 4];
                ah[3] = Ahi[(r + 8) * PSU + kb + 4];
                al[0] = Alo[r * PSU + kb];
                al[1] = Alo[(r + 8) * PSU + kb];
                al[2] = Alo[r * PSU + kb + 4];
                al[3] = Alo[(r + 8) * PSU + kb + 4];
                #pragma unroll
                for (int nt = 0; nt < 4; nt++) {
                    mma16(acc[mt][nt], ah, bh[nt]);
                    mma16(acc[mt][nt], ah, bl[nt]);
                    mma16(acc[mt][nt], al, bh[nt]);
                }
            }
        }
        __syncthreads();
    }

    // ---- epilogue ----
    #pragma unroll
    for (int mt = 0; mt < 4; mt++) {
        int rb = row0 + wm * 64 + mt * 16 + lr;
        #pragma unroll
        for (int nt = 0; nt < 4; nt++) {
            int cc = col0 + wn * 32 + nt * 8 + 2 * lc;
            #pragma unroll
            for (int half = 0; half < 2; half++) {
                int r = rb + half * 8;
                float v0 = acc[mt][nt][half * 2 + 0] * scale;
                float v1 = acc[mt][nt][half * 2 + 1] * scale;
                if (CAUSAL) {
                    if (cc > r)     v0 += NEGBIG;
                    if (cc + 1 > r) v1 += NEGBIG;
                }
                if (bias) { v0 += bias[cc]; v1 += bias[cc + 1]; }
                if (RELU) { v0 = fmaxf(v0, 0.f); v1 = fmaxf(v1, 0.f); }
                *(float2*)&C[(size_t)r * ldc + cc] = make_float2(v0, v1);
            }
        }
    }
}

// ================= SIMT GEMM (prenet only: K=234) =============
#define BM 128
#define BN 128
#define BKT 16

__global__ void __launch_bounds__(256)
gemm_nn_k(int M, int N, int K,
          const float* __restrict__ A, int lda,
          const float* __restrict__ B, int ldb,
          float* __restrict__ C, int ldc,
          const float* __restrict__ bias)
{
    __shared__ __align__(16) float As[BKT][BM];
    __shared__ __align__(16) float Bs[BKT][BN];

    int tid = threadIdx.x;
    int tx = tid & 15;
    int ty = tid >> 4;
    int row0 = blockIdx.y * BM;
    int col0 = blockIdx.x * BN;

    float acc[8][8];
    #pragma unroll
    for (int i = 0; i < 8; i++)
        #pragma unroll
        for (int j = 0; j < 8; j++) acc[i][j] = 0.f;

    for (int k0 = 0; k0 < K; k0 += BKT) {
        #pragma unroll
        for (int t = 0; t < 2; t++) {
            int slot = tid + t * 256;
            int r  = slot >> 2;
            int cq = slot & 3;
            const float* ap = A + (size_t)(row0 + r) * lda + k0 + cq * 4;
            #pragma unroll
            for (int j = 0; j < 4; j++) {
                int gk = k0 + cq * 4 + j;
                As[cq * 4 + j][r] = (gk < K) ? ap[j] : 0.f;
            }
        }
        #pragma unroll
        for (int t = 0; t < 2; t++) {
            int slot = tid + t * 256;
            int kk = slot >> 5;
            int n4 = slot & 31;
            int gk = k0 + kk;
            const float* bp = B + (size_t)gk * ldb + col0 + n4 * 4;
            #pragma unroll
            for (int j = 0; j < 4; j++)
                Bs[kk][n4 * 4 + j] = (gk < K) ? bp[j] : 0.f;
        }
        __syncthreads();

        #pragma unroll
        for (int kk = 0; kk < BKT; kk++) {
            float4 a0 = *(const float4*)&As[kk][ty * 4];
            float4 a1 = *(const float4*)&As[kk][64 + ty * 4];
            float4 b0 = *(const float4*)&Bs[kk][tx * 4];
            float4 b1 = *(const float4*)&Bs[kk][64 + tx * 4];
            float av[8] = {a0.x, a0.y, a0.z, a0.w, a1.x, a1.y, a1.z, a1.w};
            float bv[8] = {b0.x, b0.y, b0.z, b0.w, b1.x, b1.y, b1.z, b1.w};
            #pragma unroll
            for (int i = 0; i < 8; i++)
                #pragma unroll
                for (int j = 0; j < 8; j++)
                    acc[i][j] += av[i] * bv[j];
        }
        __syncthreads();
    }

    #pragma unroll
    for (int i = 0; i < 8; i++) {
        int r = row0 + ((i < 4) ? (ty * 4 + i) : (64 + ty * 4 + i - 4));
        #pragma unroll
        for (int jb = 0; jb < 2; jb++) {
            int c0 = col0 + jb * 64 + tx * 4;
            float4 v;
            float* vp = &v.x;
            #pragma unroll
            for (int j = 0; j < 4; j++)
                vp[j] = acc[i][jb * 4 + j] + bias[c0 + j];
            *(float4*)&C[(size_t)r * ldc + c0] = v;
        }
    }
}

// ---------------- block reduce helper ----------------
__device__ __forceinline__ float blockReduceSum(float v, float* s) {
    int tid = threadIdx.x;
    int nw  = blockDim.x >> 5;
    #pragma unroll
    for (int o = 16; o; o >>= 1) v += __shfl_xor_sync(0xffffffffu, v, o);
    if ((tid & 31) == 0) s[tid >> 5] = v;
    __syncthreads();
    if (tid < 32) {
        float t = (tid < nw) ? s[tid] : 0.f;
        #pragma unroll
        for (int o = 16; o; o >>= 1) t += __shfl_xor_sync(0xffffffffu, t, o);
        if (tid == 0) s[0] = t;
    }
    __syncthreads();
    float r = s[0];
    __syncthreads();
    return r;
}

// ---------------- row softmax ----------------
__global__ void softmax_k(float* __restrict__ x, int ncols) {
    x += (size_t)blockIdx.x * ncols;
    int tid = threadIdx.x;
    __shared__ float red[32];

    float mx = -3.4e38f;
    for (int i = tid; i < ncols; i += blockDim.x) mx = fmaxf(mx, x[i]);
    #pragma unroll
    for (int o = 16; o; o >>= 1) mx = fmaxf(mx, __shfl_xor_sync(0xffffffffu, mx, o));
    if ((tid & 31) == 0) red[tid >> 5] = mx;
    __syncthreads();
    if (tid < 32) {
        float t = (tid < (blockDim.x >> 5)) ? red[tid] : -3.4e38f;
        #pragma unroll
        for (int o = 16; o; o >>= 1) t = fmaxf(t, __shfl_xor_sync(0xffffffffu, t, o));
        if (tid == 0) red[0] = t;
    }
    __syncthreads();
    mx = red[0];
    __syncthreads();

    float sum = 0.f;
    for (int i = tid; i < ncols; i += blockDim.x) {
        float e = expf(x[i] - mx);
        x[i] = e;
        sum += e;
    }
    sum = blockReduceSum(sum, red);
    float inv = 1.f / sum;
    for (int i = tid; i < ncols; i += blockDim.x) x[i] *= inv;
}

// ---------------- fused x = LayerNorm(x + h) * g + b (in place) ----------------
__global__ void add_ln_k(float* __restrict__ x, const float* __restrict__ h,
                         const float* __restrict__ g, const float* __restrict__ b,
                         int ncols)
{
    size_t base = (size_t)blockIdx.x * ncols;
    int tid = threadIdx.x;
    __shared__ float red[32];

    float v[4];
    float sum = 0.f;
    int c = 0;
    for (int i = tid; i < ncols; i += blockDim.x, c++) {
        v[c] = x[base + i] + h[base + i];
        sum += v[c];
    }
    sum = blockReduceSum(sum, red);
    float mu = sum / ncols;

    float sq = 0.f;
    c = 0;
    for (int i = tid; i < ncols; i += blockDim.x, c++) {
        float d = v[c] - mu;
        sq += d * d;
    }
    sq = blockReduceSum(sq, red);
    float rstd = rsqrtf(sq / ncols + 1e-5f);

    c = 0;
    for (int i = tid; i < ncols; i += blockDim.x, c++)
        x[base + i] = (v[c] - mu) * rstd * g[i] + b[i];
}

// ---------------- scheduled sampling mix ----------------
__global__ void mix_k(float* __restrict__ x, const float* __restrict__ labels,
                      const float* __restrict__ sr, const int* __restrict__ steps,
                      int total)
{
    int i = blockIdx.x * blockDim.x + threadIdx.x;
    if (i >= total) return;
    int s = (i / cE) % cS;
    int b = i / (cE * cS);
    float thr = (float)(*steps) / 200000.0f;
    if (sr[s * cB + b] >= thr) x[i] = labels[i];
}

// ---------------- host-side dispatch ----------------
static void launch_tmma(bool transB, bool relu, bool causal,
                        int M, int N, int K,
                        const float* A, int lda, long long sAo, long long sAi,
                        const float* B, int ldb, long long sBo, long long sBi,
                        float* C, int ldc, long long sCo, long long sCi,
                        const float* bias, float scale, int nz, int innerH)
{
    dim3 blk(256);
    dim3 grd(N / 128, M / 128, nz);
    if (!transB)
        tmma_k<false, false, false><<<grd, blk, TSMEM_BYTES>>>(M, N, K, A, lda, sAo, sAi,
            B, ldb, sBo, sBi, C, ldc, sCo, sCi, bias, scale, innerH);
    else if (causal)
        tmma_k<true, false, true><<<grd, blk, TSMEM_BYTES>>>(M, N, K, A, lda, sAo, sAi,
            B, ldb, sBo, sBi, C, ldc, sCo, sCi, bias, scale, innerH);
    else if (relu)
        tmma_k<true, true, false><<<grd, blk, TSMEM_BYTES>>>(M, N, K, A, lda, sAo, sAi,
            B, ldb, sBo, sBi, C, ldc, sCo, sCi, bias, scale, innerH);
    else
        tmma_k<true, false, false><<<grd, blk, TSMEM_BYTES>>>(M, N, K, A, lda, sAo, sAi,
            B, ldb, sBo, sBi, C, ldc, sCo, sCi, bias, scale, innerH);
}

extern "C" void kernel_launch(void* const* d_in, const int* in_sizes, int n_in,
                              void* d_out, int out_size)
{
    const float* batch    = (const float*)d_in[0];
    const float* labels   = (const float*)d_in[1];
    const float* sched    = (const float*)d_in[2];
    const int*   steps    = (const int*)  d_in[3];
    const float* W_pre    = (const float*)d_in[4];
    const float* b_pre    = (const float*)d_in[5];
    const float* W_enc    = (const float*)d_in[6];
    const float* b_enc    = (const float*)d_in[7];
    const float* W_e2d    = (const float*)d_in[8];
    const float* b_e2d    = (const float*)d_in[9];
    const float* sa_in_w  = (const float*)d_in[10];
    const float* sa_in_b  = (const float*)d_in[11];
    const float* sa_out_w = (const float*)d_in[12];
    const float* sa_out_b = (const float*)d_in[13];
    const float* ca_in_w  = (const float*)d_in[14];
    const float* ca_in_b  = (const float*)d_in[15];
    const float* ca_out_w = (const float*)d_in[16];
    const float* ca_out_b = (const float*)d_in[17];
    const float* w1       = (const float*)d_in[18];
    const float* b1       = (const float*)d_in[19];
    const float* w2       = (const float*)d_in[20];
    const float* b2       = (const float*)d_in[21];
    const float* g1       = (const float*)d_in[22];
    const float* be1      = (const float*)d_in[23];
    const float* g2       = (const float*)d_in[24];
    const float* be2      = (const float*)d_in[25];
    const float* g3       = (const float*)d_in[26];
    const float* be3      = (const float*)d_in[27];

    float *x, *a, *h, *mem, *enc, *qkv, *sc, *cakv;
    cudaGetSymbolAddress((void**)&x,    g_x);
    cudaGetSymbolAddress((void**)&a,    g_a);
    cudaGetSymbolAddress((void**)&h,    g_h);
    cudaGetSymbolAddress((void**)&mem,  g_mem);
    cudaGetSymbolAddress((void**)&enc,  g_enc);
    cudaGetSymbolAddress((void**)&qkv,  g_qkv);
    cudaGetSymbolAddress((void**)&sc,   g_sc);
    cudaGetSymbolAddress((void**)&cakv, g_cakv);

    const float atscale = 1.0f / sqrtf((float)cHD);
    const long long sQb  = (long long)cS * 3 * cE;
    const long long sKVb = (long long)cS * 2 * cE;
    const long long sScb = (long long)cH * cS * cS;
    const long long sSch = (long long)cS * cS;
    const long long sAb  = (long long)cS * cE;

    // ---- prenet (K=234: SIMT) + encoder chain (NN tensor) ----
    {
        dim3 blk(256), grd(cE / BN, cM / BM, 1);
        gemm_nn_k<<<grd, blk>>>(cM, cE, cIN, batch, cIN, W_pre, cE, a, cE, b_pre);
    }
    launch_tmma(false, false, false, cM, cENC, cE,
                a, cE, 0, 0, W_enc, cENC, 0, 0, enc, cENC, 0, 0, b_enc, 1.f, 1, 1);
    launch_tmma(false, false, false, cM, cE, cENC,
                enc, cENC, 0, 0, W_e2d, cE, 0, 0, mem, cE, 0, 0, b_e2d, 1.f, 1, 1);

    cudaMemcpyAsync(x, labels, sizeof(float) * (size_t)cM * cE,
                    cudaMemcpyDeviceToDevice);

    for (int p = 0; p < 2; p++) {
        for (int l = 0; l < cL; l++) {
            const float* siw = sa_in_w + (size_t)l * 3 * cE * cE;
            const float* sib = sa_in_b + (size_t)l * 3 * cE;
            const float* ciw = ca_in_w + (size_t)l * 3 * cE * cE;
            const float* cib = ca_in_b + (size_t)l * 3 * cE;
            float* kvl = cakv + (size_t)l * cM * 2 * cE;

            // ===== self-attention =====
            launch_tmma(true, false, false, cM, 3 * cE, cE,
                        x, cE, 0, 0, siw, cE, 0, 0, qkv, 3 * cE, 0, 0, sib, 1.f, 1, 1);
            launch_tmma(true, false, true, cS, cS, cHD,
                        qkv,        3 * cE, sQb, cHD,
                        qkv + cE,   3 * cE, sQb, cHD,
                        sc, cS, sScb, sSch, nullptr, atscale, cB * cH, cH);
            softmax_k<<<cB * cH * cS, 256>>>(sc, cS);
            launch_tmma(false, false, false, cS, cHD, cS,
                        sc, cS, sScb, sSch,
                        qkv + 2 * cE, 3 * cE, sQb, cHD,
                        a, cE, sAb, cHD, nullptr, 1.f, cB * cH, cH);
            launch_tmma(true, false, false, cM, cE, cE,
                        a, cE, 0, 0, sa_out_w + (size_t)l * cE * cE, cE, 0, 0,
                        h, cE, 0, 0, sa_out_b + (size_t)l * cE, 1.f, 1, 1);
            add_ln_k<<<cM, 256>>>(x, h, g1 + (size_t)l * cE, be1 + (size_t)l * cE, cE);

            // ===== cross-attention (K/V cached across the two decoder passes) =====
            launch_tmma(true, false, false, cM, cE, cE,
                        x, cE, 0, 0, ciw, cE, 0, 0, qkv, 3 * cE, 0, 0, cib, 1.f, 1, 1);
            if (p == 0)
                launch_tmma(true, false, false, cM, 2 * cE, cE,
                            mem, cE, 0, 0, ciw + (size_t)cE * cE, cE, 0, 0,
                            kvl, 2 * cE, 0, 0, cib + cE, 1.f, 1, 1);
            launch_tmma(true, false, false, cS, cS, cHD,
                        qkv, 3 * cE, sQb, cHD,
                        kvl, 2 * cE, sKVb, cHD,
                        sc, cS, sScb, sSch, nullptr, atscale, cB * cH, cH);
            softmax_k<<<cB * cH * cS, 256>>>(sc, cS);
            launch_tmma(false, false, false, cS, cHD, cS,
                        sc, cS, sScb, sSch,
                        kvl + cE, 2 * cE, sKVb, cHD,
                        a, cE, sAb, cHD, nullptr, 1.f, cB * cH, cH);
            launch_tmma(true, false, false, cM, cE, cE,
                        a, cE, 0, 0, ca_out_w + (size_t)l * cE * cE, cE, 0, 0,
                        h, cE, 0, 0, ca_out_b + (size_t)l * cE, 1.f, 1, 1);
            add_ln_k<<<cM, 256>>>(x, h, g2 + (size_t)l * cE, be2 + (size_t)l * cE, cE);

            // ===== FFN (relu) — hidden reuses qkv scratch =====
            launch_tmma(true, true, false, cM, cFF, cE,
                        x, cE, 0, 0, w1 + (size_t)l * cFF * cE, cE, 0, 0,
                        qkv, cFF, 0, 0, b1 + (size_t)l * cFF, 1.f, 1, 1);
            launch_tmma(true, false, false, cM, cE, cFF,
                        qkv, cFF, 0, 0, w2 + (size_t)l * cE * cFF, cFF, 0, 0,
                        h, cE, 0, 0, b2 + (size_t)l * cE, 1.f, 1, 1);
            add_ln_k<<<cM, 256>>>(x, h, g3 + (size_t)l * cE, be3 + (size_t)l * cE, cE);
        }
        if (p == 0) {
            int total = cM * cE;
            mix_k<<<(total + 255) / 256, 256>>>(x, labels, sched, steps, total);
        }
    }

    cudaMemcpyAsync(d_out, x, sizeof(float) * (size_t)cM * cE,
                    cudaMemcpyDeviceToDevice);
}

// round 11
// speedup vs baseline: 5.0978x; 1.1531x over previous
#include <cuda_runtime.h>
#include <cuda_bf16.h>
#include <math.h>
#include <stdint.h>

// ---------------- problem constants ----------------
constexpr int cB = 16, cS = 512, cE = 768, cH = 2, cHD = 384;
constexpr int cFF = 256, cL = 3, cENC = 128, cIN = 234;
constexpr int cM = cB * cS;
constexpr float NEGBIG = -1e9f;

// ---------------- fp32 scratch (only what is actually read as fp32) --------
__device__ float g_x  [cM * cE];
__device__ float g_h  [cM * cE];
__device__ float g_sc [cB * cH * cS * cS];

// ---------------- bf16 hi/lo planes (activations) ----------------
__device__ __nv_bfloat16 x_h[cM * cE],      x_l[cM * cE];
__device__ __nv_bfloat16 a_h[cM * cE],      a_l[cM * cE];
__device__ __nv_bfloat16 mem_h[cM * cE],    mem_l[cM * cE];
__device__ __nv_bfloat16 enc_h[cM * cENC],  enc_l[cM * cENC];
__device__ __nv_bfloat16 qkv_h[cM * 3 * cE], qkv_l[cM * 3 * cE];
__device__ __nv_bfloat16 sc_h[cB * cH * cS * cS], sc_l[cB * cH * cS * cS];
__device__ __nv_bfloat16 cakv_h[cL * cM * 2 * cE], cakv_l[cL * cM * 2 * cE];
// ---------------- bf16 hi/lo planes (weights, split once per call) ----------
__device__ __nv_bfloat16 wsai_h[cL * 3 * cE * cE], wsai_l[cL * 3 * cE * cE];
__device__ __nv_bfloat16 wsao_h[cL * cE * cE],     wsao_l[cL * cE * cE];
__device__ __nv_bfloat16 wcai_h[cL * 3 * cE * cE], wcai_l[cL * 3 * cE * cE];
__device__ __nv_bfloat16 wcao_h[cL * cE * cE],     wcao_l[cL * cE * cE];
__device__ __nv_bfloat16 ww1_h[cL * cFF * cE],     ww1_l[cL * cFF * cE];
__device__ __nv_bfloat16 ww2_h[cL * cE * cFF],     ww2_l[cL * cE * cFF];
__device__ __nv_bfloat16 wenc_h[cE * cENC],        wenc_l[cE * cENC];
__device__ __nv_bfloat16 we2d_h[cENC * cE],        we2d_l[cENC * cE];

__device__ __forceinline__ void split1(float v, __nv_bfloat16& h, __nv_bfloat16& l) {
    h = __float2bfloat16_rn(v);
    l = __float2bfloat16_rn(v - __bfloat162float(h));
}

// ============ bf16-plane mma.sync GEMM =================
// C = A * op(B). 128x128 CTA tile, 256 thr, 8 warps (2x4), warp tile 64x32.
// Inputs are pre-split bf16 hi/lo planes; D += Ah*Bh + Ah*Bl + Al*Bh.
// cp.async staging, double-buffered smem, ldmatrix fragment loads.
// fp32 C and hi/lo plane outputs are BOTH optional (nullable).
// M, N multiples of 128; K multiple of 32.

constexpr int TBK = 32;
// per-buffer smem layout (bytes): Ahi 0 (128 rows x 80B), Alo 10240,
// Bhi 20480, Blo 30720. TN B: 128n x 80B rows. NN B: 32k x 272B rows.
constexpr int SM_BUF = 40960;
constexpr int TSMEM  = 2 * SM_BUF;   // 81920

__device__ __forceinline__ uint32_t smem_u32(const void* p) {
    uint32_t a;
    asm("{ .reg .u64 t; cvta.to.shared.u64 t, %1; cvt.u32.u64 %0, t; }"
        : "=r"(a) : "l"(p));
    return a;
}
__device__ __forceinline__ void cp16(uint32_t s, const void* g) {
    asm volatile("cp.async.ca.shared.global [%0], [%1], 16;"
                 :: "r"(s), "l"(g) : "memory");
}
__device__ __forceinline__ void ldsm4(uint32_t* r, uint32_t a) {
    asm volatile("ldmatrix.sync.aligned.m8n8.x4.shared.b16 {%0,%1,%2,%3}, [%4];"
        : "=r"(r[0]), "=r"(r[1]), "=r"(r[2]), "=r"(r[3]) : "r"(a));
}
__device__ __forceinline__ void ldsm4t(uint32_t* r, uint32_t a) {
    asm volatile("ldmatrix.sync.aligned.m8n8.x4.trans.shared.b16 {%0,%1,%2,%3}, [%4];"
        : "=r"(r[0]), "=r"(r[1]), "=r"(r[2]), "=r"(r[3]) : "r"(a));
}
__device__ __forceinline__ void mma16(float* d, const uint32_t* a, const uint32_t* b) {
    asm volatile(
        "mma.sync.aligned.m16n8k16.row.col.f32.bf16.bf16.f32 "
        "{%0,%1,%2,%3}, {%4,%5,%6,%7}, {%8,%9}, {%0,%1,%2,%3};"
        : "+f"(d[0]), "+f"(d[1]), "+f"(d[2]), "+f"(d[3])
        : "r"(a[0]), "r"(a[1]), "r"(a[2]), "r"(a[3]), "r"(b[0]), "r"(b[1]));
}

template<bool TRANSB>
__device__ __forceinline__ void stage(
    const __nv_bfloat16* __restrict__ Ah, const __nv_bfloat16* __restrict__ Al, int lda,
    const __nv_bfloat16* __restrict__ Bh, const __nv_bfloat16* __restrict__ Bl, int ldb,
    int row0, int col0, int k0, uint32_t sbuf, int tid)
{
    #pragma unroll
    for (int i = 0; i < 2; i++) {
        int s = tid + i * 256;
        int r = s >> 2, kq = s & 3;
        uint32_t off = (uint32_t)(r * 80 + kq * 16);
        size_t gidx = (size_t)(row0 + r) * lda + k0 + kq * 8;
        cp16(sbuf + off,         Ah + gidx);
        cp16(sbuf + 10240 + off, Al + gidx);
    }
    if (TRANSB) {
        #pragma unroll
        for (int i = 0; i < 2; i++) {
            int s = tid + i * 256;
            int n = s >> 2, kq = s & 3;
            uint32_t off = (uint32_t)(n * 80 + kq * 16);
            size_t gidx = (size_t)(col0 + n) * ldb + k0 + kq * 8;
            cp16(sbuf + 20480 + off, Bh + gidx);
            cp16(sbuf + 30720 + off, Bl + gidx);
        }
    } else {
        #pragma unroll
        for (int i = 0; i < 2; i++) {
            int s = tid + i * 256;
            int k = s >> 4, ns = s & 15;
            uint32_t off = (uint32_t)(k * 272 + ns * 16);
            size_t gidx = (size_t)(k0 + k) * ldb + col0 + ns * 8;
            cp16(sbuf + 20480 + off, Bh + gidx);
            cp16(sbuf + 30720 + off, Bl + gidx);
        }
    }
    asm volatile("cp.async.commit_group;" ::: "memory");
}

template<bool TRANSB, bool RELU, bool CAUSAL>
__global__ void __launch_bounds__(256)
tmma_k(int K,
       const __nv_bfloat16* __restrict__ Ah, const __nv_bfloat16* __restrict__ Al,
       int lda, long long sAo, long long sAi,
       const __nv_bfloat16* __restrict__ Bh, const __nv_bfloat16* __restrict__ Bl,
       int ldb, long long sBo, long long sBi,
       float* __restrict__ C, __nv_bfloat16* __restrict__ Chi,
       __nv_bfloat16* __restrict__ Clo,
       int ldc, long long sCo, long long sCi,
       const float* __restrict__ bias, float scale, int innerH)
{
    extern __shared__ char smraw[];
    int z  = blockIdx.z;
    int zo = z / innerH, zi = z - zo * innerH;
    Ah += zo * sAo + zi * sAi;  Al += zo * sAo + zi * sAi;
    Bh += zo * sBo + zi * sBi;  Bl += zo * sBo + zi * sBi;
    if (C) C += zo * sCo + zi * sCi;
    if (Chi) { Chi += zo * sCo + zi * sCi; Clo += zo * sCo + zi * sCi; }

    const int tid = threadIdx.x;
    const int lane = tid & 31;
    const int wid  = tid >> 5;
    const int wm = wid >> 2, wn = wid & 3;
    const int row0 = blockIdx.y * 128;
    const int col0 = blockIdx.x * 128;
    const int lr = lane >> 2, lc = lane & 3;
    const int g = lane >> 3, li = lane & 7;

    const uint32_t sb = smem_u32(smraw);

    // per-lane ldmatrix offsets
    const uint32_t aoff = (uint32_t)((wm * 64 + (g & 1) * 8 + li) * 80 + (g >> 1) * 16);
    uint32_t boff[2];
    #pragma unroll
    for (int p2 = 0; p2 < 2; p2++) {
        if (TRANSB)
            boff[p2] = (uint32_t)((wn * 32 + p2 * 16 + (g >> 1) * 8 + li) * 80 + (g & 1) * 16);
        else
            boff[p2] = (uint32_t)(((g & 1) * 8 + li) * 272 + (wn * 32 + (2 * p2 + (g >> 1)) * 8) * 2);
    }

    float acc[4][4][4];
    #pragma unroll
    for (int i = 0; i < 4; i++)
        #pragma unroll
        for (int j = 0; j < 4; j++)
            #pragma unroll
            for (int q = 0; q < 4; q++) acc[i][j][q] = 0.f;

    const int nch = K / TBK;
    stage<TRANSB>(Ah, Al, lda, Bh, Bl, ldb, row0, col0, 0, sb, tid);

    for (int c = 0; c < nch; c++) {
        int buf = c & 1;
        uint32_t sbuf = sb + buf * SM_BUF;
        if (c + 1 < nch) {
            stage<TRANSB>(Ah, Al, lda, Bh, Bl, ldb, row0, col0,
                          (c + 1) * TBK, sb + (buf ^ 1) * SM_BUF, tid);
            asm volatile("cp.async.wait_group 1;" ::: "memory");
        } else {
            asm volatile("cp.async.wait_group 0;" ::: "memory");
        }
        __syncthreads();

        #pragma unroll
        for (int ks = 0; ks < 2; ks++) {
            uint32_t bh[2][4], bl[2][4];
            #pragma unroll
            for (int p2 = 0; p2 < 2; p2++) {
                uint32_t ba = sbuf + 20480 + boff[p2] +
                              (TRANSB ? (uint32_t)(ks * 32) : (uint32_t)(ks * 16 * 272));
                if (TRANSB) { ldsm4(bh[p2], ba); ldsm4(bl[p2], ba + 10240); }
                else        { ldsm4t(bh[p2], ba); ldsm4t(bl[p2], ba + 10240); }
            }
            #pragma unroll
            for (int mt = 0; mt < 4; mt++) {
                uint32_t aa = sbuf + aoff + (uint32_t)(mt * 16 * 80 + ks * 32);
                uint32_t ah[4], al[4];
                ldsm4(ah, aa);
                ldsm4(al, aa + 10240);
                #pragma unroll
                for (int nt = 0; nt < 4; nt++) {
                    const uint32_t* bhp = &bh[nt >> 1][(nt & 1) * 2];
                    const uint32_t* blp = &bl[nt >> 1][(nt & 1) * 2];
                    mma16(acc[mt][nt], ah, bhp);
                    mma16(acc[mt][nt], ah, blp);
                    mma16(acc[mt][nt], al, bhp);
                }
            }
        }
        __syncthreads();
    }

    // ---- epilogue: optional fp32 C and optional hi/lo plane split ----
    #pragma unroll
    for (int mt = 0; mt < 4; mt++) {
        int rb = row0 + wm * 64 + mt * 16 + lr;
        #pragma unroll
        for (int nt = 0; nt < 4; nt++) {
            int cc = col0 + wn * 32 + nt * 8 + 2 * lc;
            #pragma unroll
            for (int half = 0; half < 2; half++) {
                int r = rb + half * 8;
                float v0 = acc[mt][nt][half * 2 + 0] * scale;
                float v1 = acc[mt][nt][half * 2 + 1] * scale;
                if (CAUSAL) {
                    if (cc > r)     v0 += NEGBIG;
                    if (cc + 1 > r) v1 += NEGBIG;
                }
                if (bias) { v0 += bias[cc]; v1 += bias[cc + 1]; }
                if (RELU) { v0 = fmaxf(v0, 0.f); v1 = fmaxf(v1, 0.f); }
                size_t o = (size_t)r * ldc + cc;
                if (C) *(float2*)&C[o] = make_float2(v0, v1);
                if (Chi) {
                    __nv_bfloat16 h0, l0, h1, l1;
                    split1(v0, h0, l0); split1(v1, h1, l1);
                    *(__nv_bfloat162*)&Chi[o] = __halves2bfloat162(h0, h1);
                    *(__nv_bfloat162*)&Clo[o] = __halves2bfloat162(l0, l1);
                }
            }
        }
    }
}

// ================= SIMT GEMM (prenet only: K=234) =============
// Writes hi/lo planes only (fp32 prenet output has no consumer).
#define BM 128
#define BN 128
#define BKT 16

__global__ void __launch_bounds__(256)
gemm_nn_k(int M, int N, int K,
          const float* __restrict__ A, int lda,
          const float* __restrict__ B, int ldb,
          __nv_bfloat16* __restrict__ Chi, __nv_bfloat16* __restrict__ Clo,
          int ldc, const float* __restrict__ bias)
{
    __shared__ __align__(16) float As[BKT][BM];
    __shared__ __align__(16) float Bs[BKT][BN];

    int tid = threadIdx.x;
    int tx = tid & 15, ty = tid >> 4;
    int row0 = blockIdx.y * BM, col0 = blockIdx.x * BN;

    float acc[8][8];
    #pragma unroll
    for (int i = 0; i < 8; i++)
        #pragma unroll
        for (int j = 0; j < 8; j++) acc[i][j] = 0.f;

    for (int k0 = 0; k0 < K; k0 += BKT) {
        #pragma unroll
        for (int t = 0; t < 2; t++) {
            int slot = tid + t * 256;
            int r = slot >> 2, cq = slot & 3;
            const float* ap = A + (size_t)(row0 + r) * lda + k0 + cq * 4;
            #pragma unroll
            for (int j = 0; j < 4; j++) {
                int gk = k0 + cq * 4 + j;
                As[cq * 4 + j][r] = (gk < K) ? ap[j] : 0.f;
            }
        }
        #pragma unroll
        for (int t = 0; t < 2; t++) {
            int slot = tid + t * 256;
            int kk = slot >> 5, n4 = slot & 31;
            int gk = k0 + kk;
            const float* bp = B + (size_t)gk * ldb + col0 + n4 * 4;
            #pragma unroll
            for (int j = 0; j < 4; j++)
                Bs[kk][n4 * 4 + j] = (gk < K) ? bp[j] : 0.f;
        }
        __syncthreads();

        #pragma unroll
        for (int kk = 0; kk < BKT; kk++) {
            float4 a0 = *(const float4*)&As[kk][ty * 4];
            float4 a1 = *(const float4*)&As[kk][64 + ty * 4];
            float4 b0 = *(const float4*)&Bs[kk][tx * 4];
            float4 b1 = *(const float4*)&Bs[kk][64 + tx * 4];
            float av[8] = {a0.x, a0.y, a0.z, a0.w, a1.x, a1.y, a1.z, a1.w};
            float bv[8] = {b0.x, b0.y, b0.z, b0.w, b1.x, b1.y, b1.z, b1.w};
            #pragma unroll
            for (int i = 0; i < 8; i++)
                #pragma unroll
                for (int j = 0; j < 8; j++)
                    acc[i][j] += av[i] * bv[j];
        }
        __syncthreads();
    }

    #pragma unroll
    for (int i = 0; i < 8; i++) {
        int r = row0 + ((i < 4) ? (ty * 4 + i) : (64 + ty * 4 + i - 4));
        #pragma unroll
        for (int jb = 0; jb < 2; jb++) {
            int c0 = col0 + jb * 64 + tx * 4;
            size_t o = (size_t)r * ldc + c0;
            #pragma unroll
            for (int j = 0; j < 4; j++) {
                float v = acc[i][jb * 4 + j] + bias[c0 + j];
                __nv_bfloat16 hh, ll;
                split1(v, hh, ll);
                Chi[o + j] = hh; Clo[o + j] = ll;
            }
        }
    }
}

// ---------------- split kernels ----------------
__global__ void split_k(const float* __restrict__ src,
                        __nv_bfloat16* __restrict__ hi,
                        __nv_bfloat16* __restrict__ lo, int n)
{
    int i = blockIdx.x * blockDim.x + threadIdx.x;
    if (i >= n) return;
    split1(src[i], hi[i], lo[i]);
}

__global__ void copy_split_k(float* __restrict__ dst, const float* __restrict__ src,
                             __nv_bfloat16* __restrict__ hi,
                             __nv_bfloat16* __restrict__ lo, int n)
{
    int i = blockIdx.x * blockDim.x + threadIdx.x;
    if (i >= n) return;
    float v = src[i];
    dst[i] = v;
    split1(v, hi[i], lo[i]);
}

// ---------------- block reduce ----------------
__device__ __forceinline__ float blockReduceSum(float v, float* s) {
    int tid = threadIdx.x;
    int nw = blockDim.x >> 5;
    #pragma unroll
    for (int o = 16; o; o >>= 1) v += __shfl_xor_sync(0xffffffffu, v, o);
    if ((tid & 31) == 0) s[tid >> 5] = v;
    __syncthreads();
    if (tid < 32) {
        float t = (tid < nw) ? s[tid] : 0.f;
        #pragma unroll
        for (int o = 16; o; o >>= 1) t += __shfl_xor_sync(0xffffffffu, t, o);
        if (tid == 0) s[0] = t;
    }
    __syncthreads();
    float r = s[0];
    __syncthreads();
    return r;
}

// ---------------- row softmax (+ split planes) ----------------
__global__ void softmax_k(float* __restrict__ x,
                          __nv_bfloat16* __restrict__ hi,
                          __nv_bfloat16* __restrict__ lo, int ncols)
{
    size_t base = (size_t)blockIdx.x * ncols;
    x += base; hi += base; lo += base;
    int tid = threadIdx.x;
    __shared__ float red[32];

    float mx = -3.4e38f;
    for (int i = tid; i < ncols; i += blockDim.x) mx = fmaxf(mx, x[i]);
    #pragma unroll
    for (int o = 16; o; o >>= 1) mx = fmaxf(mx, __shfl_xor_sync(0xffffffffu, mx, o));
    if ((tid & 31) == 0) red[tid >> 5] = mx;
    __syncthreads();
    if (tid < 32) {
        float t = (tid < (blockDim.x >> 5)) ? red[tid] : -3.4e38f;
        #pragma unroll
        for (int o = 16; o; o >>= 1) t = fmaxf(t, __shfl_xor_sync(0xffffffffu, t, o));
        if (tid == 0) red[0] = t;
    }
    __syncthreads();
    mx = red[0];
    __syncthreads();

    float sum = 0.f;
    for (int i = tid; i < ncols; i += blockDim.x) {
        float e = expf(x[i] - mx);
        x[i] = e;
        sum += e;
    }
    sum = blockReduceSum(sum, red);
    float inv = 1.f / sum;
    for (int i = tid; i < ncols; i += blockDim.x) {
        float v = x[i] * inv;
        split1(v, hi[i], lo[i]);
    }
}

// ---------------- fused x = LayerNorm(x + h) (+ split planes) ---------------
__global__ void add_ln_k(float* __restrict__ x, const float* __restrict__ h,
                         __nv_bfloat16* __restrict__ hi, __nv_bfloat16* __restrict__ lo,
                         const float* __restrict__ g, const float* __restrict__ b,
                         int ncols)
{
    size_t base = (size_t)blockIdx.x * ncols;
    int tid = threadIdx.x;
    __shared__ float red[32];

    float v[4];
    float sum = 0.f;
    int c = 0;
    for (int i = tid; i < ncols; i += blockDim.x, c++) {
        v[c] = x[base + i] + h[base + i];
        sum += v[c];
    }
    sum = blockReduceSum(sum, red);
    float mu = sum / ncols;

    float sq = 0.f;
    c = 0;
    for (int i = tid; i < ncols; i += blockDim.x, c++) {
        float d = v[c] - mu;
        sq += d * d;
    }
    sq = blockReduceSum(sq, red);
    float rstd = rsqrtf(sq / ncols + 1e-5f);

    c = 0;
    for (int i = tid; i < ncols; i += blockDim.x, c++) {
        float o = (v[c] - mu) * rstd * g[i] + b[i];
        x[base + i] = o;
        split1(o, hi[base + i], lo[base + i]);
    }
}

// ---------------- scheduled sampling mix (+ split planes) ----------------
__global__ void mix_k(float* __restrict__ x, const float* __restrict__ labels,
                      __nv_bfloat16* __restrict__ hi, __nv_bfloat16* __restrict__ lo,
                      const float* __restrict__ sr, const int* __restrict__ steps,
                      int total)
{
    int i = blockIdx.x * blockDim.x + threadIdx.x;
    if (i >= total) return;
    int s = (i / cE) % cS;
    int b = i / (cE * cS);
    float thr = (float)(*steps) / 200000.0f;
    float v = (sr[s * cB + b] >= thr) ? labels[i] : x[i];
    x[i] = v;
    split1(v, hi[i], lo[i]);
}

// ---------------- host dispatch ----------------
struct Planes { const __nv_bfloat16 *h, *l; };

static void launch_tmma(bool transB, bool relu, bool causal,
                        int M, int N, int K,
                        Planes A, int lda, long long sAo, long long sAi,
                        Planes B, int ldb, long long sBo, long long sBi,
                        float* C, __nv_bfloat16* Chi, __nv_bfloat16* Clo,
                        int ldc, long long sCo, long long sCi,
                        const float* bias, float scale, int nz, int innerH)
{
    dim3 blk(256);
    dim3 grd(N / 128, M / 128, nz);
    if (!transB) {
        cudaFuncSetAttribute((const void*)tmma_k<false, false, false>,
                             cudaFuncAttributeMaxDynamicSharedMemorySize, TSMEM);
        tmma_k<false, false, false><<<grd, blk, TSMEM>>>(K, A.h, A.l, lda, sAo, sAi,
            B.h, B.l, ldb, sBo, sBi, C, Chi, Clo, ldc, sCo, sCi, bias, scale, innerH);
    } else if (causal) {
        cudaFuncSetAttribute((const void*)tmma_k<true, false, true>,
                             cudaFuncAttributeMaxDynamicSharedMemorySize, TSMEM);
        tmma_k<true, false, true><<<grd, blk, TSMEM>>>(K, A.h, A.l, lda, sAo, sAi,
            B.h, B.l, ldb, sBo, sBi, C, Chi, Clo, ldc, sCo, sCi, bias, scale, innerH);
    } else if (relu) {
        cudaFuncSetAttribute((const void*)tmma_k<true, true, false>,
                             cudaFuncAttributeMaxDynamicSharedMemorySize, TSMEM);
        tmma_k<true, true, false><<<grd, blk, TSMEM>>>(K, A.h, A.l, lda, sAo, sAi,
            B.h, B.l, ldb, sBo, sBi, C, Chi, Clo, ldc, sCo, sCi, bias, scale, innerH);
    } else {
        cudaFuncSetAttribute((const void*)tmma_k<true, false, false>,
                             cudaFuncAttributeMaxDynamicSharedMemorySize, TSMEM);
        tmma_k<true, false, false><<<grd, blk, TSMEM>>>(K, A.h, A.l, lda, sAo, sAi,
            B.h, B.l, ldb, sBo, sBi, C, Chi, Clo, ldc, sCo, sCi, bias, scale, innerH);
    }
}

template<typename T>
static T* sym(T* symbol) {
    void* p = nullptr;
    cudaGetSymbolAddress(&p, (const void*)symbol);
    return (T*)p;
}

extern "C" void kernel_launch(void* const* d_in, const int* in_sizes, int n_in,
                              void* d_out, int out_size)
{
    const float* batch    = (const float*)d_in[0];
    const float* labels   = (const float*)d_in[1];
    const float* sched    = (const float*)d_in[2];
    const int*   steps    = (const int*)  d_in[3];
    const float* W_pre    = (const float*)d_in[4];
    const float* b_pre    = (const float*)d_in[5];
    const float* W_enc    = (const float*)d_in[6];
    const float* b_enc    = (const float*)d_in[7];
    const float* W_e2d    = (const float*)d_in[8];
    const float* b_e2d    = (const float*)d_in[9];
    const float* sa_in_w  = (const float*)d_in[10];
    const float* sa_in_b  = (const float*)d_in[11];
    const float* sa_out_w = (const float*)d_in[12];
    const float* sa_out_b = (const float*)d_in[13];
    const float* ca_in_w  = (const float*)d_in[14];
    const float* ca_in_b  = (const float*)d_in[15];
    const float* ca_out_w = (const float*)d_in[16];
    const float* ca_out_b = (const float*)d_in[17];
    const float* w1       = (const float*)d_in[18];
    const float* b1       = (const float*)d_in[19];
    const float* w2       = (const float*)d_in[20];
    const float* b2       = (const float*)d_in[21];
    const float* g1       = (const float*)d_in[22];
    const float* be1      = (const float*)d_in[23];
    const float* g2       = (const float*)d_in[24];
    const float* be2      = (const float*)d_in[25];
    const float* g3       = (const float*)d_in[26];
    const float* be3      = (const float*)d_in[27];

    float* x  = sym(g_x);
    float* h  = sym(g_h);
    float* sc = sym(g_sc);

    __nv_bfloat16 *xh = sym(x_h), *xl = sym(x_l);
    __nv_bfloat16 *ah = sym(a_h), *al = sym(a_l);
    __nv_bfloat16 *memh = sym(mem_h), *meml = sym(mem_l);
    __nv_bfloat16 *ench = sym(enc_h), *encl = sym(enc_l);
    __nv_bfloat16 *qkvh = sym(qkv_h), *qkvl = sym(qkv_l);
    __nv_bfloat16 *sch = sym(sc_h), *scl = sym(sc_l);
    __nv_bfloat16 *cakvh = sym(cakv_h), *cakvl = sym(cakv_l);
    __nv_bfloat16 *wsaih = sym(wsai_h), *wsail = sym(wsai_l);
    __nv_bfloat16 *wsaoh = sym(wsao_h), *wsaol = sym(wsao_l);
    __nv_bfloat16 *wcaih = sym(wcai_h), *wcail = sym(wcai_l);
    __nv_bfloat16 *wcaoh = sym(wcao_h), *wcaol = sym(wcao_l);
    __nv_bfloat16 *ww1h = sym(ww1_h), *ww1l = sym(ww1_l);
    __nv_bfloat16 *ww2h = sym(ww2_h), *ww2l = sym(ww2_l);
    __nv_bfloat16 *wench = sym(wenc_h), *wencl = sym(wenc_l);
    __nv_bfloat16 *we2dh = sym(we2d_h), *we2dl = sym(we2d_l);

    const float atscale = 1.0f / sqrtf((float)cHD);
    const long long sQb  = (long long)cS * 3 * cE;
    const long long sKVb = (long long)cS * 2 * cE;
    const long long sScb = (long long)cH * cS * cS;
    const long long sSch = (long long)cS * cS;
    const long long sAb  = (long long)cS * cE;

    // ---- weight splits (once per call) ----
    auto spl = [](const float* s, __nv_bfloat16* hh, __nv_bfloat16* ll, int n) {
        split_k<<<(n + 255) / 256, 256>>>(s, hh, ll, n);
    };
    spl(sa_in_w,  wsaih, wsail, cL * 3 * cE * cE);
    spl(sa_out_w, wsaoh, wsaol, cL * cE * cE);
    spl(ca_in_w,  wcaih, wcail, cL * 3 * cE * cE);
    spl(ca_out_w, wcaoh, wcaol, cL * cE * cE);
    spl(w1, ww1h, ww1l, cL * cFF * cE);
    spl(w2, ww2h, ww2l, cL * cE * cFF);
    spl(W_enc, wench, wencl, cE * cENC);
    spl(W_e2d, we2dh, we2dl, cENC * cE);

    // ---- prenet (SIMT, K=234, planes only) + encoder chain (NN tensor) ----
    {
        dim3 blk(256), grd(cE / BN, cM / BM, 1);
        gemm_nn_k<<<grd, blk>>>(cM, cE, cIN, batch, cIN, W_pre, cE,
                                ah, al, cE, b_pre);
    }
    launch_tmma(false, false, false, cM, cENC, cE,
                {ah, al}, cE, 0, 0, {wench, wencl}, cENC, 0, 0,
                nullptr, ench, encl, cENC, 0, 0, b_enc, 1.f, 1, 1);
    launch_tmma(false, false, false, cM, cE, cENC,
                {ench, encl}, cENC, 0, 0, {we2dh, we2dl}, cE, 0, 0,
                nullptr, memh, meml, cE, 0, 0, b_e2d, 1.f, 1, 1);

    {
        int total = cM * cE;
        copy_split_k<<<(total + 255) / 256, 256>>>(x, labels, xh, xl, total);
    }

    for (int p = 0; p < 2; p++) {
        for (int l = 0; l < cL; l++) {
            size_t wqkvOff = (size_t)l * 3 * cE * cE;
            size_t woOff   = (size_t)l * cE * cE;
            const float* sib = sa_in_b + (size_t)l * 3 * cE;
            const float* cib = ca_in_b + (size_t)l * 3 * cE;
            size_t kvOff = (size_t)l * cM * 2 * cE;

            // ===== self-attention =====
            launch_tmma(true, false, false, cM, 3 * cE, cE,
                        {xh, xl}, cE, 0, 0,
                        {wsaih + wqkvOff, wsail + wqkvOff}, cE, 0, 0,
                        nullptr, qkvh, qkvl, 3 * cE, 0, 0, sib, 1.f, 1, 1);
            launch_tmma(true, false, true, cS, cS, cHD,
                        {qkvh, qkvl}, 3 * cE, sQb, cHD,
                        {qkvh + cE, qkvl + cE}, 3 * cE, sQb, cHD,
                        sc, nullptr, nullptr, cS, sScb, sSch, nullptr, atscale,
                        cB * cH, cH);
            softmax_k<<<cB * cH * cS, 256>>>(sc, sch, scl, cS);
            launch_tmma(false, false, false, cS, cHD, cS,
                        {sch, scl}, cS, sScb, sSch,
                        {qkvh + 2 * cE, qkvl + 2 * cE}, 3 * cE, sQb, cHD,
                        nullptr, ah, al, cE, sAb, cHD, nullptr, 1.f, cB * cH, cH);
            launch_tmma(true, false, false, cM, cE, cE,
                        {ah, al}, cE, 0, 0,
                        {wsaoh + woOff, wsaol + woOff}, cE, 0, 0,
                        h, nullptr, nullptr, cE, 0, 0,
                        sa_out_b + (size_t)l * cE, 1.f, 1, 1);
            add_ln_k<<<cM, 256>>>(x, h, xh, xl,
                                  g1 + (size_t)l * cE, be1 + (size_t)l * cE, cE);

            // ===== cross-attention (K/V cached across passes) =====
            launch_tmma(true, false, false, cM, cE, cE,
                        {xh, xl}, cE, 0, 0,
                        {wcaih + wqkvOff, wcail + wqkvOff}, cE, 0, 0,
                        nullptr, qkvh, qkvl, 3 * cE, 0, 0, cib, 1.f, 1, 1);
            if (p == 0)
                launch_tmma(true, false, false, cM, 2 * cE, cE,
                            {memh, meml}, cE, 0, 0,
                            {wcaih + wqkvOff + (size_t)cE * cE,
                             wcail + wqkvOff + (size_t)cE * cE}, cE, 0, 0,
                            nullptr, cakvh + kvOff, cakvl + kvOff,
                            2 * cE, 0, 0, cib + cE, 1.f, 1, 1);
            launch_tmma(true, false, false, cS, cS, cHD,
                        {qkvh, qkvl}, 3 * cE, sQb, cHD,
                        {cakvh + kvOff, cakvl + kvOff}, 2 * cE, sKVb, cHD,
                        sc, nullptr, nullptr, cS, sScb, sSch, nullptr, atscale,
                        cB * cH, cH);
            softmax_k<<<cB * cH * cS, 256>>>(sc, sch, scl, cS);
            launch_tmma(false, false, false, cS, cHD, cS,
                        {sch, scl}, cS, sScb, sSch,
                        {cakvh + kvOff + cE, cakvl + kvOff + cE}, 2 * cE, sKVb, cHD,
                        nullptr, ah, al, cE, sAb, cHD, nullptr, 1.f, cB * cH, cH);
            launch_tmma(true, false, false, cM, cE, cE,
                        {ah, al}, cE, 0, 0,
                        {wcaoh + woOff, wcaol + woOff}, cE, 0, 0,
                        h, nullptr, nullptr, cE, 0, 0,
                        ca_out_b + (size_t)l * cE, 1.f, 1, 1);
            add_ln_k<<<cM, 256>>>(x, h, xh, xl,
                                  g2 + (size_t)l * cE, be2 + (size_t)l * cE, cE);

            // ===== FFN (relu) — hidden planes reuse qkv plane buffers =====
            launch_tmma(true, true, false, cM, cFF, cE,
                        {xh, xl}, cE, 0, 0,
                        {ww1h + (size_t)l * cFF * cE, ww1l + (size_t)l * cFF * cE},
                        cE, 0, 0,
                        nullptr, qkvh, qkvl, cFF, 0, 0, b1 + (size_t)l * cFF, 1.f, 1, 1);
            launch_tmma(true, false, false, cM, cE, cFF,
                        {qkvh, qkvl}, cFF, 0, 0,
                        {ww2h + (size_t)l * cE * cFF, ww2l + (size_t)l * cE * cFF},
                        cFF, 0, 0,
                        h, nullptr, nullptr, cE, 0, 0, b2 + (size_t)l * cE, 1.f, 1, 1);
            add_ln_k<<<cM, 256>>>(x, h, xh, xl,
                                  g3 + (size_t)l * cE, be3 + (size_t)l * cE, cE);
        }
        if (p == 0) {
            int total = cM * cE;
            mix_k<<<(total + 255) / 256, 256>>>(x, labels, xh, xl, sched, steps, total);
        }
    }

    cudaMemcpyAsync(d_out, x, sizeof(float) * (size_t)cM * cE,
                    cudaMemcpyDeviceToDevice);
}